// round 1
// baseline (speedup 1.0000x reference)
#include <cuda_runtime.h>

// Problem constants (fixed by the dataset)
#define NN 50000
#define EE 1600000

// Scratch (module-load allocated, allowed). float4 layout guarantees 16B alignment.
__device__ float4 g_S1[NN * 32];   // x @ W1              [N,128]
__device__ float4 g_h [NN * 32];   // spmm1 accum / h     [N,128]
__device__ float4 g_S2[NN * 10];   // h @ W2              [N,40]
__device__ float4 g_O [NN * 10];   // spmm2 accum         [N,40]
__device__ int    g_idx64;         // 1 if edge_index is int64, 0 if int32

__device__ __forceinline__ void red_add_v4(float* p, float4 v) {
    asm volatile("red.global.add.v4.f32 [%0], {%1,%2,%3,%4};"
                 :: "l"(p), "f"(v.x), "f"(v.y), "f"(v.z), "f"(v.w)
                 : "memory");
}

// ---------------------------------------------------------------------------
// Detect whether edge_index is int64 or int32 (JAX x64-config dependent).
// int64 values < 2^31 => every odd 32-bit word is zero. Deterministic.
// ---------------------------------------------------------------------------
__global__ void detect_kernel(const int* __restrict__ ei) {
    if (threadIdx.x == 0 && blockIdx.x == 0) {
        int is64 = 1;
        #pragma unroll 1
        for (int j = 1; j < 256; j += 2) {
            if (ei[j] != 0) { is64 = 0; break; }
        }
        g_idx64 = is64;
    }
}

__device__ __forceinline__ void load_edge(const void* ei, int e, int nedge,
                                          int& row, int& col) {
    if (g_idx64) {
        const long long* p = (const long long*)ei;
        row = (int)p[e];
        col = (int)p[nedge + e];
    } else {
        const int* p = (const int*)ei;
        row = p[e];
        col = p[nedge + e];
    }
}

// ---------------------------------------------------------------------------
// Zero the two accumulator buffers.
// ---------------------------------------------------------------------------
__global__ void zero_kernel() {
    int i = blockIdx.x * blockDim.x + threadIdx.x;
    float4 z = make_float4(0.f, 0.f, 0.f, 0.f);
    if (i < NN * 32) g_h[i] = z;
    if (i < NN * 10) g_O[i] = z;
}

// ---------------------------------------------------------------------------
// GEMM1: g_S1 = x @ W1   (n x 128) @ (128 x 128)
// 64-row tile of x in shared; W1 streamed through L1 (64KB, fully resident).
// 256 threads: thread -> 8 rows x 4 cols.
// ---------------------------------------------------------------------------
__global__ void __launch_bounds__(256) gemm1_kernel(const float* __restrict__ x,
                                                    const float* __restrict__ W1,
                                                    int n) {
    __shared__ float xs[64][128];
    int t = threadIdx.x;
    int row0 = blockIdx.x * 64;

    for (int i = t; i < 64 * 32; i += 256) {
        int r = i >> 5, c4 = i & 31;
        int gr = row0 + r;
        float4 v = (gr < n) ? ((const float4*)x)[(size_t)gr * 32 + c4]
                            : make_float4(0.f, 0.f, 0.f, 0.f);
        xs[r][c4 * 4 + 0] = v.x;
        xs[r][c4 * 4 + 1] = v.y;
        xs[r][c4 * 4 + 2] = v.z;
        xs[r][c4 * 4 + 3] = v.w;
    }
    __syncthreads();

    int rg = t >> 5;              // row group 0..7 (8 rows each)
    int c4 = (t & 31);            // float4 column 0..31
    float acc[8][4];
    #pragma unroll
    for (int i = 0; i < 8; i++)
        #pragma unroll
        for (int j = 0; j < 4; j++) acc[i][j] = 0.f;

    const float4* W4 = (const float4*)W1;
    #pragma unroll 4
    for (int k = 0; k < 128; k++) {
        float4 wv = __ldg(&W4[k * 32 + c4]);
        #pragma unroll
        for (int i = 0; i < 8; i++) {
            float xv = xs[rg * 8 + i][k];
            acc[i][0] += xv * wv.x;
            acc[i][1] += xv * wv.y;
            acc[i][2] += xv * wv.z;
            acc[i][3] += xv * wv.w;
        }
    }

    #pragma unroll
    for (int i = 0; i < 8; i++) {
        int gr = row0 + rg * 8 + i;
        if (gr < n)
            g_S1[(size_t)gr * 32 + c4] =
                make_float4(acc[i][0], acc[i][1], acc[i][2], acc[i][3]);
    }
}

// ---------------------------------------------------------------------------
// SpMM1: g_h[row] += w * g_S1[col], d=128. One thread per (edge, float4).
// ---------------------------------------------------------------------------
__global__ void spmm1_kernel(const void* __restrict__ ei,
                             const float* __restrict__ ew, int nedge) {
    unsigned i = blockIdx.x * blockDim.x + threadIdx.x;
    if (i >= (unsigned)nedge * 32u) return;
    int e = (int)(i >> 5);
    int q = (int)(i & 31u);
    int row, col;
    load_edge(ei, e, nedge, row, col);
    float wt = ew[e];
    float4 v = g_S1[(size_t)col * 32 + q];
    v.x *= wt; v.y *= wt; v.z *= wt; v.w *= wt;
    red_add_v4((float*)&g_h[(size_t)row * 32 + q], v);
}

// ---------------------------------------------------------------------------
// h = relu(h + b1)
// ---------------------------------------------------------------------------
__global__ void relu_bias_kernel(const float* __restrict__ b1, int n) {
    int i = blockIdx.x * blockDim.x + threadIdx.x;
    if (i >= n * 32) return;
    int c4 = i & 31;
    float4 b = ((const float4*)b1)[c4];
    float4 v = g_h[i];
    v.x = fmaxf(v.x + b.x, 0.f);
    v.y = fmaxf(v.y + b.y, 0.f);
    v.z = fmaxf(v.z + b.z, 0.f);
    v.w = fmaxf(v.w + b.w, 0.f);
    g_h[i] = v;
}

// ---------------------------------------------------------------------------
// GEMM2: g_S2 = h @ W2   (n x 128) @ (128 x 40)
// 32-row tile of h + full W2 in shared. 320 threads: thread -> 4 rows x 1 col.
// ---------------------------------------------------------------------------
__global__ void __launch_bounds__(320) gemm2_kernel(const float* __restrict__ W2,
                                                    int n) {
    __shared__ float hs[32][129];
    __shared__ float w2s[128 * 40];
    int t = threadIdx.x;

    for (int i = t; i < 128 * 40; i += 320) w2s[i] = W2[i];

    int row0 = blockIdx.x * 32;
    for (int i = t; i < 32 * 32; i += 320) {
        int r = i >> 5, c4 = i & 31;
        int gr = row0 + r;
        float4 v = (gr < n) ? g_h[(size_t)gr * 32 + c4]
                            : make_float4(0.f, 0.f, 0.f, 0.f);
        hs[r][c4 * 4 + 0] = v.x;
        hs[r][c4 * 4 + 1] = v.y;
        hs[r][c4 * 4 + 2] = v.z;
        hs[r][c4 * 4 + 3] = v.w;
    }
    __syncthreads();

    int col = t % 40;
    int rg  = t / 40;             // 0..7 -> rows rg*4 .. rg*4+3
    float acc[4] = {0.f, 0.f, 0.f, 0.f};
    #pragma unroll 4
    for (int k = 0; k < 128; k++) {
        float wv = w2s[k * 40 + col];
        #pragma unroll
        for (int i = 0; i < 4; i++) acc[i] += hs[rg * 4 + i][k] * wv;
    }
    float* S2f = (float*)g_S2;
    #pragma unroll
    for (int i = 0; i < 4; i++) {
        int gr = row0 + rg * 4 + i;
        if (gr < n) S2f[(size_t)gr * 40 + col] = acc[i];
    }
}

// ---------------------------------------------------------------------------
// SpMM2: g_O[row] += w * g_S2[col], d=40 (10 float4 chunks per edge).
// ---------------------------------------------------------------------------
__global__ void spmm2_kernel(const void* __restrict__ ei,
                             const float* __restrict__ ew, int nedge) {
    unsigned i = blockIdx.x * blockDim.x + threadIdx.x;
    if (i >= (unsigned)nedge * 10u) return;
    int e = (int)(i / 10u);
    int q = (int)(i - (unsigned)e * 10u);
    int row, col;
    load_edge(ei, e, nedge, row, col);
    float wt = ew[e];
    float4 v = g_S2[(size_t)col * 10 + q];
    v.x *= wt; v.y *= wt; v.z *= wt; v.w *= wt;
    red_add_v4((float*)&g_O[(size_t)row * 10 + q], v);
}

// ---------------------------------------------------------------------------
// out = log_softmax(g_O + b2), one warp per row of 40.
// ---------------------------------------------------------------------------
__global__ void lsm_kernel(const float* __restrict__ b2,
                           float* __restrict__ out, int n) {
    int w = (blockIdx.x * blockDim.x + threadIdx.x) >> 5;
    int lane = threadIdx.x & 31;
    if (w >= n) return;
    const float* o = (const float*)g_O + (size_t)w * 40;
    float v0 = o[lane] + b2[lane];
    float v1 = (lane < 8) ? (o[32 + lane] + b2[32 + lane]) : -3.0e38f;
    float m = fmaxf(v0, v1);
    #pragma unroll
    for (int off = 16; off; off >>= 1)
        m = fmaxf(m, __shfl_xor_sync(0xffffffffu, m, off));
    float s = expf(v0 - m) + ((lane < 8) ? expf(v1 - m) : 0.f);
    #pragma unroll
    for (int off = 16; off; off >>= 1)
        s += __shfl_xor_sync(0xffffffffu, s, off);
    float ls = logf(s);
    out[(size_t)w * 40 + lane] = v0 - m - ls;
    if (lane < 8)
        out[(size_t)w * 40 + 32 + lane] = v1 - m - ls;
}

// ---------------------------------------------------------------------------
// Launch
// ---------------------------------------------------------------------------
extern "C" void kernel_launch(void* const* d_in, const int* in_sizes, int n_in,
                              void* d_out, int out_size) {
    const float* x  = (const float*)d_in[0];
    const void*  ei = (const void*) d_in[1];
    const float* ew = (const float*)d_in[2];
    const float* W1 = (const float*)d_in[3];
    const float* b1 = (const float*)d_in[4];
    const float* W2 = (const float*)d_in[5];
    const float* b2 = (const float*)d_in[6];
    float* out = (float*)d_out;

    int n     = in_sizes[0] / 128;   // 50000
    int nedge = in_sizes[2];         // 1600000

    detect_kernel<<<1, 32>>>((const int*)ei);
    zero_kernel<<<(NN * 32 + 255) / 256, 256>>>();
    gemm1_kernel<<<(n + 63) / 64, 256>>>(x, W1, n);
    {
        unsigned total = (unsigned)nedge * 32u;
        spmm1_kernel<<<(total + 255) / 256, 256>>>(ei, ew, nedge);
    }
    relu_bias_kernel<<<(n * 32 + 255) / 256, 256>>>(b1, n);
    gemm2_kernel<<<(n + 31) / 32, 320>>>(W2, n);
    {
        unsigned total = (unsigned)nedge * 10u;
        spmm2_kernel<<<(total + 255) / 256, 256>>>(ei, ew, nedge);
    }
    lsm_kernel<<<(n * 32 + 255) / 256, 256>>>(b2, out, n);
}

// round 2
// speedup vs baseline: 1.1354x; 1.1354x over previous
#include <cuda_runtime.h>

#define NN 50000
#define EE 1600000

// ---------------- scratch ----------------
__device__ float4 g_S1[NN * 32];     // x @ W1        [N,128]
__device__ float4 g_h [NN * 32];     // relu(spmm1+b) [N,128]
__device__ float  g_S2[NN * 40];     // h @ W2        [N,40]
__device__ int    g_cnt[NN];         // degree histogram
__device__ int    g_start[NN + 1];   // CSR row starts
__device__ int    g_cur[NN];         // scatter cursors
__device__ int2   g_pair[EE];        // (col, weight-bits) sorted by row
__device__ int    g_idx64;

// ---------------------------------------------------------------------------
// int64 vs int32 edge_index detection (deterministic)
// ---------------------------------------------------------------------------
__global__ void detect_kernel(const int* __restrict__ ei) {
    if (threadIdx.x == 0 && blockIdx.x == 0) {
        int is64 = 1;
        #pragma unroll 1
        for (int j = 1; j < 256; j += 2)
            if (ei[j] != 0) { is64 = 0; break; }
        g_idx64 = is64;
    }
}

__device__ __forceinline__ void load_edge(const void* ei, int e, int nedge,
                                          int& row, int& col) {
    if (g_idx64) {
        const long long* p = (const long long*)ei;
        row = (int)p[e];
        col = (int)p[nedge + e];
    } else {
        const int* p = (const int*)ei;
        row = p[e];
        col = p[nedge + e];
    }
}

// ---------------------------------------------------------------------------
// CSR build: zero counts -> histogram -> scan -> scatter
// ---------------------------------------------------------------------------
__global__ void zero_cnt_kernel() {
    int i = blockIdx.x * blockDim.x + threadIdx.x;
    if (i < NN) g_cnt[i] = 0;
}

__global__ void hist_kernel(const void* __restrict__ ei, int nedge) {
    int e = blockIdx.x * blockDim.x + threadIdx.x;
    if (e >= nedge) return;
    int row, col;
    load_edge(ei, e, nedge, row, col);
    atomicAdd(&g_cnt[row], 1);
}

__global__ void __launch_bounds__(1024) scan_kernel() {
    __shared__ int part[1024];
    const int SEG = (NN + 1023) / 1024;      // 49
    int t = threadIdx.x;
    int lo = t * SEG, hi = min(lo + SEG, NN);
    int s = 0;
    for (int i = lo; i < hi; i++) s += g_cnt[i];
    part[t] = s;
    __syncthreads();
    for (int off = 1; off < 1024; off <<= 1) {
        int v = (t >= off) ? part[t - off] : 0;
        __syncthreads();
        part[t] += v;
        __syncthreads();
    }
    int run = (t > 0) ? part[t - 1] : 0;
    for (int i = lo; i < hi; i++) {
        int c = g_cnt[i];
        g_start[i] = run;
        g_cur[i]   = run;
        run += c;
    }
    if (t == 1023) g_start[NN] = part[1023];
}

__global__ void scatter_kernel(const void* __restrict__ ei,
                               const float* __restrict__ ew, int nedge) {
    int e = blockIdx.x * blockDim.x + threadIdx.x;
    if (e >= nedge) return;
    int row, col;
    load_edge(ei, e, nedge, row, col);
    float w = ew[e];
    int pos = atomicAdd(&g_cur[row], 1);
    g_pair[pos] = make_int2(col, __float_as_int(w));
}

// ---------------------------------------------------------------------------
// GEMM1: g_S1 = x @ W1   (n x 128) @ (128 x 128)
// ---------------------------------------------------------------------------
__global__ void __launch_bounds__(256) gemm1_kernel(const float* __restrict__ x,
                                                    const float* __restrict__ W1,
                                                    int n) {
    __shared__ float xs[64][128];
    int t = threadIdx.x;
    int row0 = blockIdx.x * 64;

    for (int i = t; i < 64 * 32; i += 256) {
        int r = i >> 5, c4 = i & 31;
        int gr = row0 + r;
        float4 v = (gr < n) ? ((const float4*)x)[(size_t)gr * 32 + c4]
                            : make_float4(0.f, 0.f, 0.f, 0.f);
        xs[r][c4 * 4 + 0] = v.x;
        xs[r][c4 * 4 + 1] = v.y;
        xs[r][c4 * 4 + 2] = v.z;
        xs[r][c4 * 4 + 3] = v.w;
    }
    __syncthreads();

    int rg = t >> 5;
    int c4 = t & 31;
    float acc[8][4];
    #pragma unroll
    for (int i = 0; i < 8; i++)
        #pragma unroll
        for (int j = 0; j < 4; j++) acc[i][j] = 0.f;

    const float4* W4 = (const float4*)W1;
    #pragma unroll 4
    for (int k = 0; k < 128; k++) {
        float4 wv = __ldg(&W4[k * 32 + c4]);
        #pragma unroll
        for (int i = 0; i < 8; i++) {
            float xv = xs[rg * 8 + i][k];
            acc[i][0] += xv * wv.x;
            acc[i][1] += xv * wv.y;
            acc[i][2] += xv * wv.z;
            acc[i][3] += xv * wv.w;
        }
    }
    #pragma unroll
    for (int i = 0; i < 8; i++) {
        int gr = row0 + rg * 8 + i;
        if (gr < n)
            g_S1[(size_t)gr * 32 + c4] =
                make_float4(acc[i][0], acc[i][1], acc[i][2], acc[i][3]);
    }
}

// ---------------------------------------------------------------------------
// SpMM1 (CSR gather) fused with bias + ReLU. One warp per row, lane owns a
// float4 (d = 128 = 32 lanes * 4).
// ---------------------------------------------------------------------------
__global__ void __launch_bounds__(256) spmm1_csr_kernel(const float4* __restrict__ b1,
                                                        int n) {
    int w = (blockIdx.x * blockDim.x + threadIdx.x) >> 5;
    int lane = threadIdx.x & 31;
    if (w >= n) return;

    int s = g_start[w];
    int e = g_start[w + 1];

    float ax = 0.f, ay = 0.f, az = 0.f, aw = 0.f;
    #pragma unroll 2
    for (int j = s; j < e; j++) {
        int2 p = __ldg(&g_pair[j]);               // broadcast within warp
        float wt = __int_as_float(p.y);
        float4 v = g_S1[(size_t)p.x * 32 + lane]; // 512B coalesced
        ax += wt * v.x;
        ay += wt * v.y;
        az += wt * v.z;
        aw += wt * v.w;
    }
    float4 b = __ldg(&b1[lane]);
    g_h[(size_t)w * 32 + lane] =
        make_float4(fmaxf(ax + b.x, 0.f), fmaxf(ay + b.y, 0.f),
                    fmaxf(az + b.z, 0.f), fmaxf(aw + b.w, 0.f));
}

// ---------------------------------------------------------------------------
// GEMM2: g_S2 = h @ W2   (n x 128) @ (128 x 40)
// ---------------------------------------------------------------------------
__global__ void __launch_bounds__(320) gemm2_kernel(const float* __restrict__ W2,
                                                    int n) {
    __shared__ float hs[32][129];
    __shared__ float w2s[128 * 40];
    int t = threadIdx.x;

    for (int i = t; i < 128 * 40; i += 320) w2s[i] = W2[i];

    int row0 = blockIdx.x * 32;
    for (int i = t; i < 32 * 32; i += 320) {
        int r = i >> 5, c4 = i & 31;
        int gr = row0 + r;
        float4 v = (gr < n) ? g_h[(size_t)gr * 32 + c4]
                            : make_float4(0.f, 0.f, 0.f, 0.f);
        hs[r][c4 * 4 + 0] = v.x;
        hs[r][c4 * 4 + 1] = v.y;
        hs[r][c4 * 4 + 2] = v.z;
        hs[r][c4 * 4 + 3] = v.w;
    }
    __syncthreads();

    int col = t % 40;
    int rg  = t / 40;
    float acc[4] = {0.f, 0.f, 0.f, 0.f};
    #pragma unroll 4
    for (int k = 0; k < 128; k++) {
        float wv = w2s[k * 40 + col];
        #pragma unroll
        for (int i = 0; i < 4; i++) acc[i] += hs[rg * 4 + i][k] * wv;
    }
    #pragma unroll
    for (int i = 0; i < 4; i++) {
        int gr = row0 + rg * 4 + i;
        if (gr < n) g_S2[(size_t)gr * 40 + col] = acc[i];
    }
}

// ---------------------------------------------------------------------------
// SpMM2 (CSR gather) fused with bias + log_softmax. One warp per row (d=40:
// lane owns col=lane, lanes 0-7 also own col=32+lane).
// ---------------------------------------------------------------------------
__global__ void __launch_bounds__(256) spmm2_csr_kernel(const float* __restrict__ b2,
                                                        float* __restrict__ out,
                                                        int n) {
    int w = (blockIdx.x * blockDim.x + threadIdx.x) >> 5;
    int lane = threadIdx.x & 31;
    if (w >= n) return;

    int s = g_start[w];
    int e = g_start[w + 1];

    float a0 = 0.f, a1 = 0.f;
    #pragma unroll 2
    for (int j = s; j < e; j++) {
        int2 p = __ldg(&g_pair[j]);
        float wt = __int_as_float(p.y);
        const float* src = &g_S2[(size_t)p.x * 40];
        a0 += wt * src[lane];
        if (lane < 8) a1 += wt * src[32 + lane];
    }

    float v0 = a0 + __ldg(&b2[lane]);
    float v1 = (lane < 8) ? (a1 + __ldg(&b2[32 + lane])) : -3.0e38f;

    float m = fmaxf(v0, v1);
    #pragma unroll
    for (int off = 16; off; off >>= 1)
        m = fmaxf(m, __shfl_xor_sync(0xffffffffu, m, off));
    float ssum = expf(v0 - m) + ((lane < 8) ? expf(v1 - m) : 0.f);
    #pragma unroll
    for (int off = 16; off; off >>= 1)
        ssum += __shfl_xor_sync(0xffffffffu, ssum, off);
    float ls = logf(ssum);

    out[(size_t)w * 40 + lane] = v0 - m - ls;
    if (lane < 8)
        out[(size_t)w * 40 + 32 + lane] = v1 - m - ls;
}

// ---------------------------------------------------------------------------
// Launch
// ---------------------------------------------------------------------------
extern "C" void kernel_launch(void* const* d_in, const int* in_sizes, int n_in,
                              void* d_out, int out_size) {
    const float* x  = (const float*)d_in[0];
    const void*  ei = (const void*) d_in[1];
    const float* ew = (const float*)d_in[2];
    const float* W1 = (const float*)d_in[3];
    const float* b1 = (const float*)d_in[4];
    const float* W2 = (const float*)d_in[5];
    const float* b2 = (const float*)d_in[6];
    float* out = (float*)d_out;

    int n     = in_sizes[0] / 128;   // 50000
    int nedge = in_sizes[2];         // 1600000

    detect_kernel<<<1, 32>>>((const int*)ei);
    zero_cnt_kernel<<<(NN + 255) / 256, 256>>>();
    hist_kernel<<<(nedge + 255) / 256, 256>>>(ei, nedge);
    scan_kernel<<<1, 1024>>>();
    scatter_kernel<<<(nedge + 255) / 256, 256>>>(ei, ew, nedge);

    gemm1_kernel<<<(n + 63) / 64, 256>>>(x, W1, n);
    spmm1_csr_kernel<<<(n * 32 + 255) / 256, 256>>>((const float4*)b1, n);
    gemm2_kernel<<<(n + 31) / 32, 320>>>(W2, n);
    spmm2_csr_kernel<<<(n * 32 + 255) / 256, 256>>>(b2, out, n);
}

// round 3
// speedup vs baseline: 1.4386x; 1.2671x over previous
#include <cuda_runtime.h>

#define NN 50000
#define EE 1600000

#define SCAN_T 256
#define SCAN_PER 4
#define SCAN_CHUNK (SCAN_T * SCAN_PER)                 // 1024
#define SCAN_G ((NN + SCAN_CHUNK - 1) / SCAN_CHUNK)    // 49

// ---------------- scratch ----------------
__device__ float4 g_S1[NN * 32];     // x @ W1        [N,128]
__device__ float4 g_h [NN * 32];     // relu(spmm1+b) [N,128]
__device__ float  g_S2[NN * 40];     // h @ W2        [N,40]
__device__ int    g_cnt[NN];         // degree histogram
__device__ int    g_start[NN + 1];   // CSR row starts
__device__ int    g_cur[NN];         // scatter cursors
__device__ int2   g_pair[EE];        // (col, weight-bits) grouped by row
__device__ int    g_bsum[SCAN_G];    // per-block sums
__device__ int    g_boff[SCAN_G];    // per-block exclusive offsets
__device__ int    g_idx64;

// ---------------------------------------------------------------------------
// int64 vs int32 edge_index detection (deterministic)
// ---------------------------------------------------------------------------
__global__ void detect_kernel(const int* __restrict__ ei) {
    if (threadIdx.x == 0 && blockIdx.x == 0) {
        int is64 = 1;
        #pragma unroll 1
        for (int j = 1; j < 256; j += 2)
            if (ei[j] != 0) { is64 = 0; break; }
        g_idx64 = is64;
    }
}

__device__ __forceinline__ void load_edge(const void* ei, int e, int nedge,
                                          int& row, int& col) {
    if (g_idx64) {
        const long long* p = (const long long*)ei;
        row = (int)p[e];
        col = (int)p[nedge + e];
    } else {
        const int* p = (const int*)ei;
        row = p[e];
        col = p[nedge + e];
    }
}

// ---------------------------------------------------------------------------
// CSR build: zero -> hist -> (blocksum, bscan, cscan) -> scatter
// ---------------------------------------------------------------------------
__global__ void zero_cnt_kernel() {
    int i = blockIdx.x * blockDim.x + threadIdx.x;
    if (i < NN) g_cnt[i] = 0;
}

__global__ void hist_kernel(const void* __restrict__ ei, int nedge) {
    int e = blockIdx.x * blockDim.x + threadIdx.x;
    if (e >= nedge) return;
    int row, col;
    load_edge(ei, e, nedge, row, col);
    atomicAdd(&g_cnt[row], 1);
}

// Phase 1: per-block sums (49 blocks x 256 threads x 4 elems)
__global__ void __launch_bounds__(SCAN_T) blocksum_kernel() {
    __shared__ int ws[SCAN_T / 32];
    int t = threadIdx.x;
    int base = blockIdx.x * SCAN_CHUNK + t * SCAN_PER;
    int s = 0;
    #pragma unroll
    for (int i = 0; i < SCAN_PER; i++) {
        int idx = base + i;
        if (idx < NN) s += g_cnt[idx];
    }
    #pragma unroll
    for (int off = 16; off; off >>= 1)
        s += __shfl_xor_sync(0xffffffffu, s, off);
    if ((t & 31) == 0) ws[t >> 5] = s;
    __syncthreads();
    if (t < 32) {
        int v = (t < SCAN_T / 32) ? ws[t] : 0;
        #pragma unroll
        for (int off = 16; off; off >>= 1)
            v += __shfl_xor_sync(0xffffffffu, v, off);
        if (t == 0) g_bsum[blockIdx.x] = v;
    }
}

// Phase 2: one warp scans the 49 block sums (exclusive)
__global__ void bscan_kernel() {
    int t = threadIdx.x;                       // 64 threads
    __shared__ int sh[64];
    int v = (t < SCAN_G) ? g_bsum[t] : 0;
    sh[t] = v;
    __syncthreads();
    for (int off = 1; off < 64; off <<= 1) {
        int u = (t >= off) ? sh[t - off] : 0;
        __syncthreads();
        sh[t] += u;
        __syncthreads();
    }
    if (t < SCAN_G) g_boff[t] = sh[t] - v;     // exclusive
    if (t == 63) g_start[NN] = sh[63];
}

// Phase 3: intra-block exclusive scan + offset, write g_start / g_cur
__global__ void __launch_bounds__(SCAN_T) cscan_kernel() {
    __shared__ int tsum[SCAN_T];
    int t = threadIdx.x;
    int base = blockIdx.x * SCAN_CHUNK + t * SCAN_PER;

    int c[SCAN_PER];
    int s = 0;
    #pragma unroll
    for (int i = 0; i < SCAN_PER; i++) {
        int idx = base + i;
        c[i] = (idx < NN) ? g_cnt[idx] : 0;
        s += c[i];
    }
    tsum[t] = s;
    __syncthreads();
    for (int off = 1; off < SCAN_T; off <<= 1) {
        int u = (t >= off) ? tsum[t - off] : 0;
        __syncthreads();
        tsum[t] += u;
        __syncthreads();
    }
    int run = g_boff[blockIdx.x] + tsum[t] - s;   // exclusive prefix for this thread
    #pragma unroll
    for (int i = 0; i < SCAN_PER; i++) {
        int idx = base + i;
        if (idx < NN) {
            g_start[idx] = run;
            g_cur[idx]   = run;
            run += c[i];
        }
    }
}

__global__ void scatter_kernel(const void* __restrict__ ei,
                               const float* __restrict__ ew, int nedge) {
    int e = blockIdx.x * blockDim.x + threadIdx.x;
    if (e >= nedge) return;
    int row, col;
    load_edge(ei, e, nedge, row, col);
    float w = ew[e];
    int pos = atomicAdd(&g_cur[row], 1);
    g_pair[pos] = make_int2(col, __float_as_int(w));
}

// ---------------------------------------------------------------------------
// GEMM1: g_S1 = x @ W1   (n x 128) @ (128 x 128)
// ---------------------------------------------------------------------------
__global__ void __launch_bounds__(256) gemm1_kernel(const float* __restrict__ x,
                                                    const float* __restrict__ W1,
                                                    int n) {
    __shared__ float xs[64][128];
    int t = threadIdx.x;
    int row0 = blockIdx.x * 64;

    for (int i = t; i < 64 * 32; i += 256) {
        int r = i >> 5, c4 = i & 31;
        int gr = row0 + r;
        float4 v = (gr < n) ? ((const float4*)x)[(size_t)gr * 32 + c4]
                            : make_float4(0.f, 0.f, 0.f, 0.f);
        xs[r][c4 * 4 + 0] = v.x;
        xs[r][c4 * 4 + 1] = v.y;
        xs[r][c4 * 4 + 2] = v.z;
        xs[r][c4 * 4 + 3] = v.w;
    }
    __syncthreads();

    int rg = t >> 5;
    int c4 = t & 31;
    float acc[8][4];
    #pragma unroll
    for (int i = 0; i < 8; i++)
        #pragma unroll
        for (int j = 0; j < 4; j++) acc[i][j] = 0.f;

    const float4* W4 = (const float4*)W1;
    #pragma unroll 4
    for (int k = 0; k < 128; k++) {
        float4 wv = __ldg(&W4[k * 32 + c4]);
        #pragma unroll
        for (int i = 0; i < 8; i++) {
            float xv = xs[rg * 8 + i][k];
            acc[i][0] += xv * wv.x;
            acc[i][1] += xv * wv.y;
            acc[i][2] += xv * wv.z;
            acc[i][3] += xv * wv.w;
        }
    }
    #pragma unroll
    for (int i = 0; i < 8; i++) {
        int gr = row0 + rg * 8 + i;
        if (gr < n)
            g_S1[(size_t)gr * 32 + c4] =
                make_float4(acc[i][0], acc[i][1], acc[i][2], acc[i][3]);
    }
}

// ---------------------------------------------------------------------------
// SpMM1 (CSR gather) fused with bias + ReLU. One warp per row.
// ---------------------------------------------------------------------------
__global__ void __launch_bounds__(256) spmm1_csr_kernel(const float4* __restrict__ b1,
                                                        int n) {
    int w = (blockIdx.x * blockDim.x + threadIdx.x) >> 5;
    int lane = threadIdx.x & 31;
    if (w >= n) return;

    int s = g_start[w];
    int e = g_start[w + 1];

    float ax = 0.f, ay = 0.f, az = 0.f, aw = 0.f;
    #pragma unroll 2
    for (int j = s; j < e; j++) {
        int2 p = __ldg(&g_pair[j]);
        float wt = __int_as_float(p.y);
        float4 v = g_S1[(size_t)p.x * 32 + lane];
        ax += wt * v.x;
        ay += wt * v.y;
        az += wt * v.z;
        aw += wt * v.w;
    }
    float4 b = __ldg(&b1[lane]);
    g_h[(size_t)w * 32 + lane] =
        make_float4(fmaxf(ax + b.x, 0.f), fmaxf(ay + b.y, 0.f),
                    fmaxf(az + b.z, 0.f), fmaxf(aw + b.w, 0.f));
}

// ---------------------------------------------------------------------------
// GEMM2: g_S2 = h @ W2   (n x 128) @ (128 x 40)
// ---------------------------------------------------------------------------
__global__ void __launch_bounds__(320) gemm2_kernel(const float* __restrict__ W2,
                                                    int n) {
    __shared__ float hs[32][129];
    __shared__ float w2s[128 * 40];
    int t = threadIdx.x;

    for (int i = t; i < 128 * 40; i += 320) w2s[i] = W2[i];

    int row0 = blockIdx.x * 32;
    for (int i = t; i < 32 * 32; i += 320) {
        int r = i >> 5, c4 = i & 31;
        int gr = row0 + r;
        float4 v = (gr < n) ? g_h[(size_t)gr * 32 + c4]
                            : make_float4(0.f, 0.f, 0.f, 0.f);
        hs[r][c4 * 4 + 0] = v.x;
        hs[r][c4 * 4 + 1] = v.y;
        hs[r][c4 * 4 + 2] = v.z;
        hs[r][c4 * 4 + 3] = v.w;
    }
    __syncthreads();

    int col = t % 40;
    int rg  = t / 40;
    float acc[4] = {0.f, 0.f, 0.f, 0.f};
    #pragma unroll 4
    for (int k = 0; k < 128; k++) {
        float wv = w2s[k * 40 + col];
        #pragma unroll
        for (int i = 0; i < 4; i++) acc[i] += hs[rg * 4 + i][k] * wv;
    }
    #pragma unroll
    for (int i = 0; i < 4; i++) {
        int gr = row0 + rg * 4 + i;
        if (gr < n) g_S2[(size_t)gr * 40 + col] = acc[i];
    }
}

// ---------------------------------------------------------------------------
// SpMM2 (CSR gather) fused with bias + log_softmax. One warp per row.
// ---------------------------------------------------------------------------
__global__ void __launch_bounds__(256) spmm2_csr_kernel(const float* __restrict__ b2,
                                                        float* __restrict__ out,
                                                        int n) {
    int w = (blockIdx.x * blockDim.x + threadIdx.x) >> 5;
    int lane = threadIdx.x & 31;
    if (w >= n) return;

    int s = g_start[w];
    int e = g_start[w + 1];

    float a0 = 0.f, a1 = 0.f;
    #pragma unroll 2
    for (int j = s; j < e; j++) {
        int2 p = __ldg(&g_pair[j]);
        float wt = __int_as_float(p.y);
        const float* src = &g_S2[(size_t)p.x * 40];
        a0 += wt * src[lane];
        if (lane < 8) a1 += wt * src[32 + lane];
    }

    float v0 = a0 + __ldg(&b2[lane]);
    float v1 = (lane < 8) ? (a1 + __ldg(&b2[32 + lane])) : -3.0e38f;

    float m = fmaxf(v0, v1);
    #pragma unroll
    for (int off = 16; off; off >>= 1)
        m = fmaxf(m, __shfl_xor_sync(0xffffffffu, m, off));
    float ssum = expf(v0 - m) + ((lane < 8) ? expf(v1 - m) : 0.f);
    #pragma unroll
    for (int off = 16; off; off >>= 1)
        ssum += __shfl_xor_sync(0xffffffffu, ssum, off);
    float ls = logf(ssum);

    out[(size_t)w * 40 + lane] = v0 - m - ls;
    if (lane < 8)
        out[(size_t)w * 40 + 32 + lane] = v1 - m - ls;
}

// ---------------------------------------------------------------------------
// Launch
// ---------------------------------------------------------------------------
extern "C" void kernel_launch(void* const* d_in, const int* in_sizes, int n_in,
                              void* d_out, int out_size) {
    const float* x  = (const float*)d_in[0];
    const void*  ei = (const void*) d_in[1];
    const float* ew = (const float*)d_in[2];
    const float* W1 = (const float*)d_in[3];
    const float* b1 = (const float*)d_in[4];
    const float* W2 = (const float*)d_in[5];
    const float* b2 = (const float*)d_in[6];
    float* out = (float*)d_out;

    int n     = in_sizes[0] / 128;   // 50000
    int nedge = in_sizes[2];         // 1600000

    detect_kernel<<<1, 32>>>((const int*)ei);
    zero_cnt_kernel<<<(NN + 255) / 256, 256>>>();
    hist_kernel<<<(nedge + 255) / 256, 256>>>(ei, nedge);
    blocksum_kernel<<<SCAN_G, SCAN_T>>>();
    bscan_kernel<<<1, 64>>>();
    cscan_kernel<<<SCAN_G, SCAN_T>>>();
    scatter_kernel<<<(nedge + 255) / 256, 256>>>(ei, ew, nedge);

    gemm1_kernel<<<(n + 63) / 64, 256>>>(x, W1, n);
    spmm1_csr_kernel<<<(n * 32 + 255) / 256, 256>>>((const float4*)b1, n);
    gemm2_kernel<<<(n + 31) / 32, 320>>>(W2, n);
    spmm2_csr_kernel<<<(n * 32 + 255) / 256, 256>>>(b2, out, n);
}

// round 4
// speedup vs baseline: 1.7484x; 1.2153x over previous
#include <cuda_runtime.h>
#include <cuda_fp16.h>

#define NN 50000
#define EE 1600000

#define SCAN_T 256
#define SCAN_PER 4
#define SCAN_CHUNK (SCAN_T * SCAN_PER)                 // 1024
#define SCAN_G ((NN + SCAN_CHUNK - 1) / SCAN_CHUNK)    // 49

// ---------------- scratch ----------------
__device__ uint2  g_S1h[NN * 32];    // x @ W1  as fp16   [N,128] (4 halves / uint2)
__device__ float4 g_h  [NN * 32];    // relu(spmm1 + b1)  [N,128] fp32
__device__ __half g_S2h[NN * 40];    // h @ W2  as fp16   [N,40]
__device__ int    g_cnt[NN];
__device__ int    g_start[NN + 1];
__device__ int    g_cur[NN];
__device__ int2   g_pair[EE];        // (col, weight-bits) grouped by row
__device__ int    g_bsum[SCAN_G];
__device__ int    g_boff[SCAN_G];
__device__ int    g_idx64;

// ---------------------------------------------------------------------------
// int64 vs int32 edge_index detection (deterministic)
// ---------------------------------------------------------------------------
__global__ void detect_kernel(const int* __restrict__ ei) {
    if (threadIdx.x == 0 && blockIdx.x == 0) {
        int is64 = 1;
        #pragma unroll 1
        for (int j = 1; j < 256; j += 2)
            if (ei[j] != 0) { is64 = 0; break; }
        g_idx64 = is64;
    }
}

__device__ __forceinline__ void load_edge(const void* ei, int e, int nedge,
                                          int& row, int& col) {
    if (g_idx64) {
        const long long* p = (const long long*)ei;
        row = (int)p[e];
        col = (int)p[nedge + e];
    } else {
        const int* p = (const int*)ei;
        row = p[e];
        col = p[nedge + e];
    }
}

// ---------------------------------------------------------------------------
// CSR build
// ---------------------------------------------------------------------------
__global__ void zero_cnt_kernel() {
    int i = blockIdx.x * blockDim.x + threadIdx.x;
    if (i < NN) g_cnt[i] = 0;
}

__global__ void hist_kernel(const void* __restrict__ ei, int nedge) {
    int e = blockIdx.x * blockDim.x + threadIdx.x;
    if (e >= nedge) return;
    int row;
    if (g_idx64) row = (int)((const long long*)ei)[e];
    else         row = ((const int*)ei)[e];
    atomicAdd(&g_cnt[row], 1);
}

__global__ void __launch_bounds__(SCAN_T) blocksum_kernel() {
    __shared__ int ws[SCAN_T / 32];
    int t = threadIdx.x;
    int base = blockIdx.x * SCAN_CHUNK + t * SCAN_PER;
    int s = 0;
    #pragma unroll
    for (int i = 0; i < SCAN_PER; i++) {
        int idx = base + i;
        if (idx < NN) s += g_cnt[idx];
    }
    #pragma unroll
    for (int off = 16; off; off >>= 1)
        s += __shfl_xor_sync(0xffffffffu, s, off);
    if ((t & 31) == 0) ws[t >> 5] = s;
    __syncthreads();
    if (t < 32) {
        int v = (t < SCAN_T / 32) ? ws[t] : 0;
        #pragma unroll
        for (int off = 16; off; off >>= 1)
            v += __shfl_xor_sync(0xffffffffu, v, off);
        if (t == 0) g_bsum[blockIdx.x] = v;
    }
}

__global__ void bscan_kernel() {
    int t = threadIdx.x;                       // 64 threads
    __shared__ int sh[64];
    int v = (t < SCAN_G) ? g_bsum[t] : 0;
    sh[t] = v;
    __syncthreads();
    for (int off = 1; off < 64; off <<= 1) {
        int u = (t >= off) ? sh[t - off] : 0;
        __syncthreads();
        sh[t] += u;
        __syncthreads();
    }
    if (t < SCAN_G) g_boff[t] = sh[t] - v;
    if (t == 63) g_start[NN] = sh[63];
}

__global__ void __launch_bounds__(SCAN_T) cscan_kernel() {
    __shared__ int tsum[SCAN_T];
    int t = threadIdx.x;
    int base = blockIdx.x * SCAN_CHUNK + t * SCAN_PER;

    int c[SCAN_PER];
    int s = 0;
    #pragma unroll
    for (int i = 0; i < SCAN_PER; i++) {
        int idx = base + i;
        c[i] = (idx < NN) ? g_cnt[idx] : 0;
        s += c[i];
    }
    tsum[t] = s;
    __syncthreads();
    for (int off = 1; off < SCAN_T; off <<= 1) {
        int u = (t >= off) ? tsum[t - off] : 0;
        __syncthreads();
        tsum[t] += u;
        __syncthreads();
    }
    int run = g_boff[blockIdx.x] + tsum[t] - s;
    #pragma unroll
    for (int i = 0; i < SCAN_PER; i++) {
        int idx = base + i;
        if (idx < NN) {
            g_start[idx] = run;
            g_cur[idx]   = run;
            run += c[i];
        }
    }
}

__global__ void scatter_kernel(const void* __restrict__ ei,
                               const float* __restrict__ ew, int nedge) {
    int e = blockIdx.x * blockDim.x + threadIdx.x;
    if (e >= nedge) return;
    int row, col;
    load_edge(ei, e, nedge, row, col);
    float w = ew[e];
    int pos = atomicAdd(&g_cur[row], 1);
    g_pair[pos] = make_int2(col, __float_as_int(w));
}

// ---------------------------------------------------------------------------
// GEMM1: g_S1h = fp16(x @ W1)   (n x 128) @ (128 x 128)
// ---------------------------------------------------------------------------
__global__ void __launch_bounds__(256) gemm1_kernel(const float* __restrict__ x,
                                                    const float* __restrict__ W1,
                                                    int n) {
    __shared__ float xs[64][128];
    int t = threadIdx.x;
    int row0 = blockIdx.x * 64;

    for (int i = t; i < 64 * 32; i += 256) {
        int r = i >> 5, c4 = i & 31;
        int gr = row0 + r;
        float4 v = (gr < n) ? ((const float4*)x)[(size_t)gr * 32 + c4]
                            : make_float4(0.f, 0.f, 0.f, 0.f);
        xs[r][c4 * 4 + 0] = v.x;
        xs[r][c4 * 4 + 1] = v.y;
        xs[r][c4 * 4 + 2] = v.z;
        xs[r][c4 * 4 + 3] = v.w;
    }
    __syncthreads();

    int rg = t >> 5;
    int c4 = t & 31;
    float acc[8][4];
    #pragma unroll
    for (int i = 0; i < 8; i++)
        #pragma unroll
        for (int j = 0; j < 4; j++) acc[i][j] = 0.f;

    const float4* W4 = (const float4*)W1;
    #pragma unroll 4
    for (int k = 0; k < 128; k++) {
        float4 wv = __ldg(&W4[k * 32 + c4]);
        #pragma unroll
        for (int i = 0; i < 8; i++) {
            float xv = xs[rg * 8 + i][k];
            acc[i][0] += xv * wv.x;
            acc[i][1] += xv * wv.y;
            acc[i][2] += xv * wv.z;
            acc[i][3] += xv * wv.w;
        }
    }
    #pragma unroll
    for (int i = 0; i < 8; i++) {
        int gr = row0 + rg * 8 + i;
        if (gr < n) {
            __half2 h0 = __floats2half2_rn(acc[i][0], acc[i][1]);
            __half2 h1 = __floats2half2_rn(acc[i][2], acc[i][3]);
            uint2 u;
            u.x = *(const unsigned*)&h0;
            u.y = *(const unsigned*)&h1;
            g_S1h[(size_t)gr * 32 + c4] = u;
        }
    }
}

// ---------------------------------------------------------------------------
// SpMM1 (CSR gather, fp16 source) fused with bias + ReLU. One warp per row.
// ---------------------------------------------------------------------------
__global__ void __launch_bounds__(256) spmm1_csr_kernel(const float4* __restrict__ b1,
                                                        int n) {
    int w = (blockIdx.x * blockDim.x + threadIdx.x) >> 5;
    int lane = threadIdx.x & 31;
    if (w >= n) return;

    int s = g_start[w];
    int e = g_start[w + 1];

    float ax = 0.f, ay = 0.f, az = 0.f, aw = 0.f;
    #pragma unroll 2
    for (int j = s; j < e; j++) {
        int2 p = __ldg(&g_pair[j]);
        float wt = __int_as_float(p.y);
        uint2 u = g_S1h[(size_t)p.x * 32 + lane];   // 256B coalesced per warp
        float2 f0 = __half22float2(*(const __half2*)&u.x);
        float2 f1 = __half22float2(*(const __half2*)&u.y);
        ax += wt * f0.x;
        ay += wt * f0.y;
        az += wt * f1.x;
        aw += wt * f1.y;
    }
    float4 b = __ldg(&b1[lane]);
    g_h[(size_t)w * 32 + lane] =
        make_float4(fmaxf(ax + b.x, 0.f), fmaxf(ay + b.y, 0.f),
                    fmaxf(az + b.z, 0.f), fmaxf(aw + b.w, 0.f));
}

// ---------------------------------------------------------------------------
// GEMM2: g_S2h = fp16(h @ W2)   (n x 128) @ (128 x 40)
// ---------------------------------------------------------------------------
__global__ void __launch_bounds__(320) gemm2_kernel(const float* __restrict__ W2,
                                                    int n) {
    __shared__ float hs[32][129];
    __shared__ float w2s[128 * 40];
    int t = threadIdx.x;

    for (int i = t; i < 128 * 40; i += 320) w2s[i] = W2[i];

    int row0 = blockIdx.x * 32;
    for (int i = t; i < 32 * 32; i += 320) {
        int r = i >> 5, c4 = i & 31;
        int gr = row0 + r;
        float4 v = (gr < n) ? g_h[(size_t)gr * 32 + c4]
                            : make_float4(0.f, 0.f, 0.f, 0.f);
        hs[r][c4 * 4 + 0] = v.x;
        hs[r][c4 * 4 + 1] = v.y;
        hs[r][c4 * 4 + 2] = v.z;
        hs[r][c4 * 4 + 3] = v.w;
    }
    __syncthreads();

    int col = t % 40;
    int rg  = t / 40;
    float acc[4] = {0.f, 0.f, 0.f, 0.f};
    #pragma unroll 4
    for (int k = 0; k < 128; k++) {
        float wv = w2s[k * 40 + col];
        #pragma unroll
        for (int i = 0; i < 4; i++) acc[i] += hs[rg * 4 + i][k] * wv;
    }
    #pragma unroll
    for (int i = 0; i < 4; i++) {
        int gr = row0 + rg * 4 + i;
        if (gr < n) g_S2h[(size_t)gr * 40 + col] = __float2half_rn(acc[i]);
    }
}

// ---------------------------------------------------------------------------
// SpMM2 (CSR gather, fp16 source) fused with bias + log_softmax.
// One warp per row; lanes 0..19 each own 2 adjacent cols (half2).
// ---------------------------------------------------------------------------
__global__ void __launch_bounds__(256) spmm2_csr_kernel(const float* __restrict__ b2,
                                                        float* __restrict__ out,
                                                        int n) {
    int w = (blockIdx.x * blockDim.x + threadIdx.x) >> 5;
    int lane = threadIdx.x & 31;
    if (w >= n) return;

    int s = g_start[w];
    int e = g_start[w + 1];
    bool act = (lane < 20);

    float a0 = 0.f, a1 = 0.f;
    #pragma unroll 2
    for (int j = s; j < e; j++) {
        int2 p = __ldg(&g_pair[j]);
        float wt = __int_as_float(p.y);
        if (act) {
            __half2 hv = ((const __half2*)(g_S2h + (size_t)p.x * 40))[lane];
            float2 f = __half22float2(hv);
            a0 += wt * f.x;
            a1 += wt * f.y;
        }
    }

    float v0 = act ? (a0 + __ldg(&b2[2 * lane]))     : -3.0e38f;
    float v1 = act ? (a1 + __ldg(&b2[2 * lane + 1])) : -3.0e38f;

    float m = fmaxf(v0, v1);
    #pragma unroll
    for (int off = 16; off; off >>= 1)
        m = fmaxf(m, __shfl_xor_sync(0xffffffffu, m, off));
    float ssum = act ? (expf(v0 - m) + expf(v1 - m)) : 0.f;
    #pragma unroll
    for (int off = 16; off; off >>= 1)
        ssum += __shfl_xor_sync(0xffffffffu, ssum, off);
    float ls = logf(ssum);

    if (act)
        ((float2*)out)[(size_t)w * 20 + lane] =
            make_float2(v0 - m - ls, v1 - m - ls);
}

// ---------------------------------------------------------------------------
// Launch: CSR build on stream 0, gemm1 forked onto aux stream, join at spmm1.
// ---------------------------------------------------------------------------
extern "C" void kernel_launch(void* const* d_in, const int* in_sizes, int n_in,
                              void* d_out, int out_size) {
    const float* x  = (const float*)d_in[0];
    const void*  ei = (const void*) d_in[1];
    const float* ew = (const float*)d_in[2];
    const float* W1 = (const float*)d_in[3];
    const float* b1 = (const float*)d_in[4];
    const float* W2 = (const float*)d_in[5];
    const float* b2 = (const float*)d_in[6];
    float* out = (float*)d_out;

    int n     = in_sizes[0] / 128;   // 50000
    int nedge = in_sizes[2];         // 1600000

    static cudaStream_t s_aux = nullptr;
    static cudaEvent_t ev_fork = nullptr, ev_join = nullptr;
    if (s_aux == nullptr) {
        cudaStreamCreateWithFlags(&s_aux, cudaStreamNonBlocking);
        cudaEventCreateWithFlags(&ev_fork, cudaEventDisableTiming);
        cudaEventCreateWithFlags(&ev_join, cudaEventDisableTiming);
    }

    // Fork: gemm1 (independent of edges) runs concurrently with CSR build.
    cudaEventRecord(ev_fork, 0);
    cudaStreamWaitEvent(s_aux, ev_fork, 0);
    gemm1_kernel<<<(n + 63) / 64, 256, 0, s_aux>>>(x, W1, n);
    cudaEventRecord(ev_join, s_aux);

    // CSR build on stream 0
    detect_kernel<<<1, 32>>>((const int*)ei);
    zero_cnt_kernel<<<(NN + 255) / 256, 256>>>();
    hist_kernel<<<(nedge + 255) / 256, 256>>>(ei, nedge);
    blocksum_kernel<<<SCAN_G, SCAN_T>>>();
    bscan_kernel<<<1, 64>>>();
    cscan_kernel<<<SCAN_G, SCAN_T>>>();
    scatter_kernel<<<(nedge + 255) / 256, 256>>>(ei, ew, nedge);

    // Join, then the dependent chain
    cudaStreamWaitEvent(0, ev_join, 0);
    spmm1_csr_kernel<<<(n * 32 + 255) / 256, 256>>>((const float4*)b1, n);
    gemm2_kernel<<<(n + 31) / 32, 320>>>(W2, n);
    spmm2_csr_kernel<<<(n * 32 + 255) / 256, 256>>>(b2, out, n);
}

// round 5
// speedup vs baseline: 1.7700x; 1.0123x over previous
#include <cuda_runtime.h>
#include <cuda_fp16.h>

#define NN 50000
#define EE 1600000

#define SCAN_T 256
#define SCAN_PER 4
#define SCAN_CHUNK (SCAN_T * SCAN_PER)                 // 1024
#define SCAN_G ((NN + SCAN_CHUNK - 1) / SCAN_CHUNK)    // 49

// ---------------- scratch ----------------
__device__ uint2    g_S1h[NN * 32];   // x @ W1  as fp16   [N,128]
__device__ float4   g_h  [NN * 32];   // relu(spmm1 + b1)  [N,128] fp32
__device__ __half   g_S2h[NN * 40];   // h @ W2  as fp16   [N,40]
__device__ int      g_cnt[NN];
__device__ int      g_start[NN + 1];
__device__ int      g_cur[NN];
__device__ unsigned g_pairp[EE];      // (col<<16) | fp16(weight), grouped by row
__device__ int      g_bsum[SCAN_G];
__device__ int      g_boff[SCAN_G];
__device__ int      g_idx64;

// ---------------------------------------------------------------------------
// int64 vs int32 detection — parallel ballot (odd 32-bit words all zero => i64)
// ---------------------------------------------------------------------------
__global__ void detect_kernel(const int* __restrict__ ei) {
    int lane = threadIdx.x & 31;
    int nz0 = (ei[2 * lane + 1] != 0) ? 1 : 0;
    int nz1 = (ei[2 * (lane + 32) + 1] != 0) ? 1 : 0;
    unsigned b = __ballot_sync(0xffffffffu, nz0 | nz1);
    if (lane == 0) g_idx64 = (b == 0u) ? 1 : 0;
}

// ---------------------------------------------------------------------------
// CSR build
// ---------------------------------------------------------------------------
__global__ void zero_cnt_kernel() {
    int i = blockIdx.x * blockDim.x + threadIdx.x;
    if (i < NN) g_cnt[i] = 0;
}

// 4 edges per thread, vectorized row loads
__global__ void hist_kernel(const void* __restrict__ ei, int nedge) {
    int t = blockIdx.x * blockDim.x + threadIdx.x;
    int e0 = t * 4;
    if (e0 >= nedge) return;
    int r[4];
    int cnt = min(4, nedge - e0);
    if (g_idx64) {
        const int4* p = (const int4*)ei;     // 2 int64 per int4
        int4 v0 = p[t * 2];
        int4 v1 = p[t * 2 + 1];
        r[0] = v0.x; r[1] = v0.z; r[2] = v1.x; r[3] = v1.z;
    } else {
        int4 v = ((const int4*)ei)[t];
        r[0] = v.x; r[1] = v.y; r[2] = v.z; r[3] = v.w;
    }
    #pragma unroll
    for (int i = 0; i < 4; i++)
        if (i < cnt) atomicAdd(&g_cnt[r[i]], 1);
}

__global__ void __launch_bounds__(SCAN_T) blocksum_kernel() {
    __shared__ int ws[SCAN_T / 32];
    int t = threadIdx.x;
    int base = blockIdx.x * SCAN_CHUNK + t * SCAN_PER;
    int s = 0;
    #pragma unroll
    for (int i = 0; i < SCAN_PER; i++) {
        int idx = base + i;
        if (idx < NN) s += g_cnt[idx];
    }
    #pragma unroll
    for (int off = 16; off; off >>= 1)
        s += __shfl_xor_sync(0xffffffffu, s, off);
    if ((t & 31) == 0) ws[t >> 5] = s;
    __syncthreads();
    if (t < 32) {
        int v = (t < SCAN_T / 32) ? ws[t] : 0;
        #pragma unroll
        for (int off = 16; off; off >>= 1)
            v += __shfl_xor_sync(0xffffffffu, v, off);
        if (t == 0) g_bsum[blockIdx.x] = v;
    }
}

__global__ void bscan_kernel() {
    int t = threadIdx.x;                       // 64 threads
    __shared__ int sh[64];
    int v = (t < SCAN_G) ? g_bsum[t] : 0;
    sh[t] = v;
    __syncthreads();
    for (int off = 1; off < 64; off <<= 1) {
        int u = (t >= off) ? sh[t - off] : 0;
        __syncthreads();
        sh[t] += u;
        __syncthreads();
    }
    if (t < SCAN_G) g_boff[t] = sh[t] - v;
    if (t == 63) g_start[NN] = sh[63];
}

__global__ void __launch_bounds__(SCAN_T) cscan_kernel() {
    __shared__ int tsum[SCAN_T];
    int t = threadIdx.x;
    int base = blockIdx.x * SCAN_CHUNK + t * SCAN_PER;

    int c[SCAN_PER];
    int s = 0;
    #pragma unroll
    for (int i = 0; i < SCAN_PER; i++) {
        int idx = base + i;
        c[i] = (idx < NN) ? g_cnt[idx] : 0;
        s += c[i];
    }
    tsum[t] = s;
    __syncthreads();
    for (int off = 1; off < SCAN_T; off <<= 1) {
        int u = (t >= off) ? tsum[t - off] : 0;
        __syncthreads();
        tsum[t] += u;
        __syncthreads();
    }
    int run = g_boff[blockIdx.x] + tsum[t] - s;
    #pragma unroll
    for (int i = 0; i < SCAN_PER; i++) {
        int idx = base + i;
        if (idx < NN) {
            g_start[idx] = run;
            g_cur[idx]   = run;
            run += c[i];
        }
    }
}

// 2 edges per thread, packed pair (col<<16 | fp16 weight)
__global__ void scatter_kernel(const void* __restrict__ ei,
                               const float* __restrict__ ew, int nedge) {
    int t = blockIdx.x * blockDim.x + threadIdx.x;
    int e0 = t * 2;
    if (e0 >= nedge) return;
    int r0, r1, c0, c1;
    if (g_idx64) {
        const int4* p = (const int4*)ei;
        int4 rv = p[t];                       // rows 2t, 2t+1
        int4 cv = p[nedge / 2 + t];           // cols 2t, 2t+1
        r0 = rv.x; r1 = rv.z; c0 = cv.x; c1 = cv.z;
    } else {
        const int2* p = (const int2*)ei;
        int2 rv = p[t];
        int2 cv = p[nedge / 2 + t];
        r0 = rv.x; r1 = rv.y; c0 = cv.x; c1 = cv.y;
    }
    float2 w = ((const float2*)ew)[t];
    {
        unsigned pk = ((unsigned)c0 << 16) |
                      (unsigned)__half_as_ushort(__float2half_rn(w.x));
        int pos = atomicAdd(&g_cur[r0], 1);
        g_pairp[pos] = pk;
    }
    if (e0 + 1 < nedge) {
        unsigned pk = ((unsigned)c1 << 16) |
                      (unsigned)__half_as_ushort(__float2half_rn(w.y));
        int pos = atomicAdd(&g_cur[r1], 1);
        g_pairp[pos] = pk;
    }
}

// ---------------------------------------------------------------------------
// GEMM1 (tf32 tensor cores): g_S1h = fp16(x @ W1)
// Block: 256 threads (8 warps: 4 m-groups x 2 n-groups), tile 128x128, K=128.
// Dynamic smem: xs[128][132] + ws[128][132] fp32 (135168 B).
// ---------------------------------------------------------------------------
__device__ __forceinline__ unsigned f2tf32(float f) {
    unsigned u;
    asm("cvt.rna.tf32.f32 %0, %1;" : "=r"(u) : "f"(f));
    return u;
}

__global__ void __launch_bounds__(256) gemm1_tc_kernel(const float* __restrict__ x,
                                                       const float* __restrict__ W1,
                                                       int n) {
    extern __shared__ float smem[];
    float (*xs)[132] = (float(*)[132])smem;
    float (*ws)[132] = (float(*)[132])(smem + 128 * 132);

    int t = threadIdx.x;
    int row0 = blockIdx.x * 128;

    const float4* X4 = (const float4*)x;
    const float4* W4 = (const float4*)W1;
    for (int i = t; i < 128 * 32; i += 256) {
        int r = i >> 5, c4 = i & 31;
        int gr = row0 + r;
        float4 v = (gr < n) ? X4[(size_t)gr * 32 + c4]
                            : make_float4(0.f, 0.f, 0.f, 0.f);
        *(float4*)&xs[r][c4 * 4] = v;
    }
    for (int i = t; i < 128 * 32; i += 256) {
        int r = i >> 5, c4 = i & 31;
        *(float4*)&ws[r][c4 * 4] = W4[r * 32 + c4];
    }
    __syncthreads();

    int lane = t & 31;
    int wid  = t >> 5;
    int mw = wid >> 1;        // 0..3 -> rows mw*32
    int nw = wid & 1;         // 0..1 -> cols nw*64

    float acc[2][8][4];
    #pragma unroll
    for (int a = 0; a < 2; a++)
        #pragma unroll
        for (int b = 0; b < 8; b++)
            #pragma unroll
            for (int c = 0; c < 4; c++) acc[a][b][c] = 0.f;

    int lr = lane >> 2;       // 0..7
    int lc = lane & 3;        // 0..3

    #pragma unroll 1
    for (int kt = 0; kt < 16; kt++) {
        int k = kt * 8;
        unsigned A[2][4];
        #pragma unroll
        for (int mt = 0; mt < 2; mt++) {
            int r = mw * 32 + mt * 16 + lr;
            A[mt][0] = f2tf32(xs[r    ][k + lc]);
            A[mt][1] = f2tf32(xs[r + 8][k + lc]);
            A[mt][2] = f2tf32(xs[r    ][k + lc + 4]);
            A[mt][3] = f2tf32(xs[r + 8][k + lc + 4]);
        }
        #pragma unroll
        for (int nt = 0; nt < 8; nt++) {
            int cn = nw * 64 + nt * 8 + lr;
            unsigned b0 = f2tf32(ws[k + lc    ][cn]);
            unsigned b1 = f2tf32(ws[k + lc + 4][cn]);
            #pragma unroll
            for (int mt = 0; mt < 2; mt++) {
                asm volatile(
                    "mma.sync.aligned.m16n8k8.row.col.f32.tf32.tf32.f32 "
                    "{%0,%1,%2,%3}, {%4,%5,%6,%7}, {%8,%9}, {%0,%1,%2,%3};"
                    : "+f"(acc[mt][nt][0]), "+f"(acc[mt][nt][1]),
                      "+f"(acc[mt][nt][2]), "+f"(acc[mt][nt][3])
                    : "r"(A[mt][0]), "r"(A[mt][1]), "r"(A[mt][2]), "r"(A[mt][3]),
                      "r"(b0), "r"(b1));
            }
        }
    }

    __half2* dst = (__half2*)g_S1h;          // row stride = 64 half2
    #pragma unroll
    for (int mt = 0; mt < 2; mt++) {
        #pragma unroll
        for (int nt = 0; nt < 8; nt++) {
            int row = row0 + mw * 32 + mt * 16 + lr;
            int col = nw * 64 + nt * 8 + lc * 2;
            if (row < n)
                dst[(size_t)row * 64 + (col >> 1)] =
                    __floats2half2_rn(acc[mt][nt][0], acc[mt][nt][1]);
            if (row + 8 < n)
                dst[(size_t)(row + 8) * 64 + (col >> 1)] =
                    __floats2half2_rn(acc[mt][nt][2], acc[mt][nt][3]);
        }
    }
}

// ---------------------------------------------------------------------------
// SpMM1 (CSR gather, fp16 src, packed pair) + bias + ReLU. One warp per row.
// ---------------------------------------------------------------------------
__global__ void __launch_bounds__(256) spmm1_csr_kernel(const float4* __restrict__ b1,
                                                        int n) {
    int w = (blockIdx.x * blockDim.x + threadIdx.x) >> 5;
    int lane = threadIdx.x & 31;
    if (w >= n) return;

    int s = g_start[w];
    int e = g_start[w + 1];

    float ax = 0.f, ay = 0.f, az = 0.f, aw = 0.f;
    #pragma unroll 2
    for (int j = s; j < e; j++) {
        unsigned p = __ldg(&g_pairp[j]);
        float wt = __half2float(__ushort_as_half((unsigned short)(p & 0xffffu)));
        int col = (int)(p >> 16);
        uint2 u = g_S1h[(size_t)col * 32 + lane];
        float2 f0 = __half22float2(*(const __half2*)&u.x);
        float2 f1 = __half22float2(*(const __half2*)&u.y);
        ax += wt * f0.x;
        ay += wt * f0.y;
        az += wt * f1.x;
        aw += wt * f1.y;
    }
    float4 b = __ldg(&b1[lane]);
    g_h[(size_t)w * 32 + lane] =
        make_float4(fmaxf(ax + b.x, 0.f), fmaxf(ay + b.y, 0.f),
                    fmaxf(az + b.z, 0.f), fmaxf(aw + b.w, 0.f));
}

// ---------------------------------------------------------------------------
// GEMM2: g_S2h = fp16(h @ W2)   (n x 128) @ (128 x 40)
// ---------------------------------------------------------------------------
__global__ void __launch_bounds__(320) gemm2_kernel(const float* __restrict__ W2,
                                                    int n) {
    __shared__ float hs[32][129];
    __shared__ float w2s[128 * 40];
    int t = threadIdx.x;

    for (int i = t; i < 128 * 40; i += 320) w2s[i] = W2[i];

    int row0 = blockIdx.x * 32;
    for (int i = t; i < 32 * 32; i += 320) {
        int r = i >> 5, c4 = i & 31;
        int gr = row0 + r;
        float4 v = (gr < n) ? g_h[(size_t)gr * 32 + c4]
                            : make_float4(0.f, 0.f, 0.f, 0.f);
        hs[r][c4 * 4 + 0] = v.x;
        hs[r][c4 * 4 + 1] = v.y;
        hs[r][c4 * 4 + 2] = v.z;
        hs[r][c4 * 4 + 3] = v.w;
    }
    __syncthreads();

    int col = t % 40;
    int rg  = t / 40;
    float acc[4] = {0.f, 0.f, 0.f, 0.f};
    #pragma unroll 4
    for (int k = 0; k < 128; k++) {
        float wv = w2s[k * 40 + col];
        #pragma unroll
        for (int i = 0; i < 4; i++) acc[i] += hs[rg * 4 + i][k] * wv;
    }
    #pragma unroll
    for (int i = 0; i < 4; i++) {
        int gr = row0 + rg * 4 + i;
        if (gr < n) g_S2h[(size_t)gr * 40 + col] = __float2half_rn(acc[i]);
    }
}

// ---------------------------------------------------------------------------
// SpMM2 (CSR gather, fp16 src, packed pair) + bias + log_softmax.
// One warp per row; lanes 0..19 own 2 adjacent cols (half2).
// ---------------------------------------------------------------------------
__global__ void __launch_bounds__(256) spmm2_csr_kernel(const float* __restrict__ b2,
                                                        float* __restrict__ out,
                                                        int n) {
    int w = (blockIdx.x * blockDim.x + threadIdx.x) >> 5;
    int lane = threadIdx.x & 31;
    if (w >= n) return;

    int s = g_start[w];
    int e = g_start[w + 1];
    bool act = (lane < 20);

    float a0 = 0.f, a1 = 0.f;
    #pragma unroll 2
    for (int j = s; j < e; j++) {
        unsigned p = __ldg(&g_pairp[j]);
        float wt = __half2float(__ushort_as_half((unsigned short)(p & 0xffffu)));
        int col = (int)(p >> 16);
        if (act) {
            __half2 hv = ((const __half2*)(g_S2h + (size_t)col * 40))[lane];
            float2 f = __half22float2(hv);
            a0 += wt * f.x;
            a1 += wt * f.y;
        }
    }

    float v0 = act ? (a0 + __ldg(&b2[2 * lane]))     : -3.0e38f;
    float v1 = act ? (a1 + __ldg(&b2[2 * lane + 1])) : -3.0e38f;

    float m = fmaxf(v0, v1);
    #pragma unroll
    for (int off = 16; off; off >>= 1)
        m = fmaxf(m, __shfl_xor_sync(0xffffffffu, m, off));
    float ssum = act ? (expf(v0 - m) + expf(v1 - m)) : 0.f;
    #pragma unroll
    for (int off = 16; off; off >>= 1)
        ssum += __shfl_xor_sync(0xffffffffu, ssum, off);
    float ls = logf(ssum);

    if (act)
        ((float2*)out)[(size_t)w * 20 + lane] =
            make_float2(v0 - m - ls, v1 - m - ls);
}

// ---------------------------------------------------------------------------
// Launch: fork gemm1 (tensor) onto aux stream vs CSR build; join at spmm1.
// ---------------------------------------------------------------------------
extern "C" void kernel_launch(void* const* d_in, const int* in_sizes, int n_in,
                              void* d_out, int out_size) {
    const float* x  = (const float*)d_in[0];
    const void*  ei = (const void*) d_in[1];
    const float* ew = (const float*)d_in[2];
    const float* W1 = (const float*)d_in[3];
    const float* b1 = (const float*)d_in[4];
    const float* W2 = (const float*)d_in[5];
    const float* b2 = (const float*)d_in[6];
    float* out = (float*)d_out;

    int n     = in_sizes[0] / 128;   // 50000
    int nedge = in_sizes[2];         // 1600000

    const int GEMM1_SMEM = 2 * 128 * 132 * sizeof(float);   // 135168

    static cudaStream_t s_aux = nullptr;
    static cudaEvent_t ev_fork = nullptr, ev_join = nullptr;
    if (s_aux == nullptr) {
        cudaStreamCreateWithFlags(&s_aux, cudaStreamNonBlocking);
        cudaEventCreateWithFlags(&ev_fork, cudaEventDisableTiming);
        cudaEventCreateWithFlags(&ev_join, cudaEventDisableTiming);
        cudaFuncSetAttribute(gemm1_tc_kernel,
                             cudaFuncAttributeMaxDynamicSharedMemorySize,
                             GEMM1_SMEM);
    }

    // Fork: gemm1 runs concurrently with CSR build.
    cudaEventRecord(ev_fork, 0);
    cudaStreamWaitEvent(s_aux, ev_fork, 0);
    gemm1_tc_kernel<<<(n + 127) / 128, 256, GEMM1_SMEM, s_aux>>>(x, W1, n);
    cudaEventRecord(ev_join, s_aux);

    // CSR build on stream 0
    detect_kernel<<<1, 32>>>((const int*)ei);
    zero_cnt_kernel<<<(NN + 255) / 256, 256>>>();
    hist_kernel<<<(nedge / 4 + 255) / 256, 256>>>(ei, nedge);
    blocksum_kernel<<<SCAN_G, SCAN_T>>>();
    bscan_kernel<<<1, 64>>>();
    cscan_kernel<<<SCAN_G, SCAN_T>>>();
    scatter_kernel<<<(nedge / 2 + 255) / 256, 256>>>(ei, ew, nedge);

    // Join, then the dependent chain
    cudaStreamWaitEvent(0, ev_join, 0);
    spmm1_csr_kernel<<<(n * 32 + 255) / 256, 256>>>((const float4*)b1, n);
    gemm2_kernel<<<(n + 31) / 32, 320>>>(W2, n);
    spmm2_csr_kernel<<<(n * 32 + 255) / 256, 256>>>(b2, out, n);
}

// round 6
// speedup vs baseline: 1.8428x; 1.0411x over previous
#include <cuda_runtime.h>
#include <cuda_fp16.h>

#define NN 50000
#define EE 1600000

#define SCAN_T 256
#define SCAN_PER 4
#define SCAN_CHUNK (SCAN_T * SCAN_PER)                 // 1024
#define SCAN_G ((NN + SCAN_CHUNK - 1) / SCAN_CHUNK)    // 49

// ---------------- scratch ----------------
__device__ uint2          g_S1h[NN * 32];   // x @ W1 as fp16      [N,128]
__device__ uint2          g_hh [NN * 32];   // relu(spmm1+b1) fp16 [N,128]
__device__ __half         g_S2h[NN * 40];   // h @ W2 as fp16      [N,40]
__device__ int            g_cnt[NN];
__device__ int            g_start[NN + 1];
__device__ unsigned short g_rank[EE];       // rank of edge within its row
__device__ unsigned       g_pairp[EE];      // (col<<16) | fp16(weight), by row
__device__ int            g_bsum[SCAN_G];
__device__ int            g_boff[SCAN_G];
__device__ int            g_idx64;

// ---------------------------------------------------------------------------
// int64 vs int32 detection — parallel ballot
// ---------------------------------------------------------------------------
__global__ void detect_kernel(const int* __restrict__ ei) {
    int lane = threadIdx.x & 31;
    int nz0 = (ei[2 * lane + 1] != 0) ? 1 : 0;
    int nz1 = (ei[2 * (lane + 32) + 1] != 0) ? 1 : 0;
    unsigned b = __ballot_sync(0xffffffffu, nz0 | nz1);
    if (lane == 0) g_idx64 = (b == 0u) ? 1 : 0;
}

// ---------------------------------------------------------------------------
// hist: 8 edges/thread; atomicAdd return value IS the edge's rank in its row.
// ---------------------------------------------------------------------------
__global__ void hist_kernel(const void* __restrict__ ei, int nedge) {
    int t = blockIdx.x * blockDim.x + threadIdx.x;
    int e0 = t * 8;
    if (e0 >= nedge) return;
    int r[8];
    if (e0 + 8 <= nedge) {
        if (g_idx64) {
            const int4* p = (const int4*)ei;
            #pragma unroll
            for (int i = 0; i < 4; i++) {
                int4 v = p[t * 4 + i];
                r[2 * i] = v.x; r[2 * i + 1] = v.z;
            }
        } else {
            const int4* p = (const int4*)ei;
            int4 a = p[t * 2], b = p[t * 2 + 1];
            r[0] = a.x; r[1] = a.y; r[2] = a.z; r[3] = a.w;
            r[4] = b.x; r[5] = b.y; r[6] = b.z; r[7] = b.w;
        }
        unsigned rk[8];
        #pragma unroll
        for (int i = 0; i < 8; i++)
            rk[i] = (unsigned)atomicAdd(&g_cnt[r[i]], 1);
        uint4 pk;
        pk.x = rk[0] | (rk[1] << 16);
        pk.y = rk[2] | (rk[3] << 16);
        pk.z = rk[4] | (rk[5] << 16);
        pk.w = rk[6] | (rk[7] << 16);
        *(uint4*)(g_rank + e0) = pk;
    } else {
        for (int i = 0; i < 8 && e0 + i < nedge; i++) {
            int row = g_idx64 ? (int)((const long long*)ei)[e0 + i]
                              : ((const int*)ei)[e0 + i];
            g_rank[e0 + i] = (unsigned short)atomicAdd(&g_cnt[row], 1);
        }
    }
}

// ---------------------------------------------------------------------------
// scan (3 phases)
// ---------------------------------------------------------------------------
__global__ void __launch_bounds__(SCAN_T) blocksum_kernel() {
    __shared__ int ws[SCAN_T / 32];
    int t = threadIdx.x;
    int base = blockIdx.x * SCAN_CHUNK + t * SCAN_PER;
    int s = 0;
    #pragma unroll
    for (int i = 0; i < SCAN_PER; i++) {
        int idx = base + i;
        if (idx < NN) s += g_cnt[idx];
    }
    #pragma unroll
    for (int off = 16; off; off >>= 1)
        s += __shfl_xor_sync(0xffffffffu, s, off);
    if ((t & 31) == 0) ws[t >> 5] = s;
    __syncthreads();
    if (t < 32) {
        int v = (t < SCAN_T / 32) ? ws[t] : 0;
        #pragma unroll
        for (int off = 16; off; off >>= 1)
            v += __shfl_xor_sync(0xffffffffu, v, off);
        if (t == 0) g_bsum[blockIdx.x] = v;
    }
}

__global__ void bscan_kernel() {
    int t = threadIdx.x;                       // 64 threads
    __shared__ int sh[64];
    int v = (t < SCAN_G) ? g_bsum[t] : 0;
    sh[t] = v;
    __syncthreads();
    for (int off = 1; off < 64; off <<= 1) {
        int u = (t >= off) ? sh[t - off] : 0;
        __syncthreads();
        sh[t] += u;
        __syncthreads();
    }
    if (t < SCAN_G) g_boff[t] = sh[t] - v;
    if (t == 63) g_start[NN] = sh[63];
}

__global__ void __launch_bounds__(SCAN_T) cscan_kernel() {
    __shared__ int tsum[SCAN_T];
    int t = threadIdx.x;
    int base = blockIdx.x * SCAN_CHUNK + t * SCAN_PER;

    int c[SCAN_PER];
    int s = 0;
    #pragma unroll
    for (int i = 0; i < SCAN_PER; i++) {
        int idx = base + i;
        c[i] = (idx < NN) ? g_cnt[idx] : 0;
        s += c[i];
    }
    tsum[t] = s;
    __syncthreads();
    for (int off = 1; off < SCAN_T; off <<= 1) {
        int u = (t >= off) ? tsum[t - off] : 0;
        __syncthreads();
        tsum[t] += u;
        __syncthreads();
    }
    int run = g_boff[blockIdx.x] + tsum[t] - s;
    #pragma unroll
    for (int i = 0; i < SCAN_PER; i++) {
        int idx = base + i;
        if (idx < NN) {
            g_start[idx] = run;
            run += c[i];
        }
    }
}

// ---------------------------------------------------------------------------
// scatter: atomic-free, 4 edges/thread. pos = start[row] + rank[e].
// ---------------------------------------------------------------------------
__global__ void scatter_kernel(const void* __restrict__ ei,
                               const float* __restrict__ ew, int nedge) {
    int t = blockIdx.x * blockDim.x + threadIdx.x;
    int e0 = t * 4;
    if (e0 >= nedge) return;
    if (e0 + 4 <= nedge) {
        int r[4], c[4];
        if (g_idx64) {
            const int4* p = (const int4*)ei;
            int4 a = p[t * 2], b = p[t * 2 + 1];
            r[0] = a.x; r[1] = a.z; r[2] = b.x; r[3] = b.z;
            const int4* q = p + (size_t)nedge / 2;
            int4 ca = q[t * 2], cb = q[t * 2 + 1];
            c[0] = ca.x; c[1] = ca.z; c[2] = cb.x; c[3] = cb.z;
        } else {
            const int4* p = (const int4*)ei;
            int4 a = p[t];
            r[0] = a.x; r[1] = a.y; r[2] = a.z; r[3] = a.w;
            int4 ca = p[nedge / 4 + t];
            c[0] = ca.x; c[1] = ca.y; c[2] = ca.z; c[3] = ca.w;
        }
        float4 w = ((const float4*)ew)[t];
        float wv[4] = {w.x, w.y, w.z, w.w};
        ushort4 rk = *(const ushort4*)(g_rank + e0);
        unsigned short rka[4] = {rk.x, rk.y, rk.z, rk.w};
        #pragma unroll
        for (int i = 0; i < 4; i++) {
            int pos = g_start[r[i]] + (int)rka[i];
            g_pairp[pos] = ((unsigned)c[i] << 16) |
                           (unsigned)__half_as_ushort(__float2half_rn(wv[i]));
        }
    } else {
        for (int i = 0; i < 4 && e0 + i < nedge; i++) {
            int row, col;
            if (g_idx64) {
                row = (int)((const long long*)ei)[e0 + i];
                col = (int)((const long long*)ei)[nedge + e0 + i];
            } else {
                row = ((const int*)ei)[e0 + i];
                col = ((const int*)ei)[nedge + e0 + i];
            }
            int pos = g_start[row] + (int)g_rank[e0 + i];
            g_pairp[pos] = ((unsigned)col << 16) |
                           (unsigned)__half_as_ushort(__float2half_rn(ew[e0 + i]));
        }
    }
}

// ---------------------------------------------------------------------------
// GEMM1 (tf32 tensor cores): g_S1h = fp16(x @ W1), tile 128x128, K=128
// ---------------------------------------------------------------------------
__device__ __forceinline__ unsigned f2tf32(float f) {
    unsigned u;
    asm("cvt.rna.tf32.f32 %0, %1;" : "=r"(u) : "f"(f));
    return u;
}

__global__ void __launch_bounds__(256) gemm1_tc_kernel(const float* __restrict__ x,
                                                       const float* __restrict__ W1,
                                                       int n) {
    extern __shared__ float smem[];
    float (*xs)[132] = (float(*)[132])smem;
    float (*ws)[132] = (float(*)[132])(smem + 128 * 132);

    int t = threadIdx.x;
    int row0 = blockIdx.x * 128;

    const float4* X4 = (const float4*)x;
    const float4* W4 = (const float4*)W1;
    for (int i = t; i < 128 * 32; i += 256) {
        int r = i >> 5, c4 = i & 31;
        int gr = row0 + r;
        float4 v = (gr < n) ? X4[(size_t)gr * 32 + c4]
                            : make_float4(0.f, 0.f, 0.f, 0.f);
        *(float4*)&xs[r][c4 * 4] = v;
    }
    for (int i = t; i < 128 * 32; i += 256) {
        int r = i >> 5, c4 = i & 31;
        *(float4*)&ws[r][c4 * 4] = W4[r * 32 + c4];
    }
    __syncthreads();

    int lane = t & 31;
    int wid  = t >> 5;
    int mw = wid >> 1;
    int nw = wid & 1;

    float acc[2][8][4];
    #pragma unroll
    for (int a = 0; a < 2; a++)
        #pragma unroll
        for (int b = 0; b < 8; b++)
            #pragma unroll
            for (int c = 0; c < 4; c++) acc[a][b][c] = 0.f;

    int lr = lane >> 2;
    int lc = lane & 3;

    #pragma unroll 1
    for (int kt = 0; kt < 16; kt++) {
        int k = kt * 8;
        unsigned A[2][4];
        #pragma unroll
        for (int mt = 0; mt < 2; mt++) {
            int r = mw * 32 + mt * 16 + lr;
            A[mt][0] = f2tf32(xs[r    ][k + lc]);
            A[mt][1] = f2tf32(xs[r + 8][k + lc]);
            A[mt][2] = f2tf32(xs[r    ][k + lc + 4]);
            A[mt][3] = f2tf32(xs[r + 8][k + lc + 4]);
        }
        #pragma unroll
        for (int nt = 0; nt < 8; nt++) {
            int cn = nw * 64 + nt * 8 + lr;
            unsigned b0 = f2tf32(ws[k + lc    ][cn]);
            unsigned b1 = f2tf32(ws[k + lc + 4][cn]);
            #pragma unroll
            for (int mt = 0; mt < 2; mt++) {
                asm volatile(
                    "mma.sync.aligned.m16n8k8.row.col.f32.tf32.tf32.f32 "
                    "{%0,%1,%2,%3}, {%4,%5,%6,%7}, {%8,%9}, {%0,%1,%2,%3};"
                    : "+f"(acc[mt][nt][0]), "+f"(acc[mt][nt][1]),
                      "+f"(acc[mt][nt][2]), "+f"(acc[mt][nt][3])
                    : "r"(A[mt][0]), "r"(A[mt][1]), "r"(A[mt][2]), "r"(A[mt][3]),
                      "r"(b0), "r"(b1));
            }
        }
    }

    __half2* dst = (__half2*)g_S1h;
    #pragma unroll
    for (int mt = 0; mt < 2; mt++) {
        #pragma unroll
        for (int nt = 0; nt < 8; nt++) {
            int row = row0 + mw * 32 + mt * 16 + lr;
            int col = nw * 64 + nt * 8 + lc * 2;
            if (row < n)
                dst[(size_t)row * 64 + (col >> 1)] =
                    __floats2half2_rn(acc[mt][nt][0], acc[mt][nt][1]);
            if (row + 8 < n)
                dst[(size_t)(row + 8) * 64 + (col >> 1)] =
                    __floats2half2_rn(acc[mt][nt][2], acc[mt][nt][3]);
        }
    }
}

// ---------------------------------------------------------------------------
// SpMM1 chunk [r0, r0+cnt): CSR gather + bias + ReLU, fp16 in/out.
// ---------------------------------------------------------------------------
__global__ void __launch_bounds__(256) spmm1_csr_kernel(const float4* __restrict__ b1,
                                                        int r0, int cnt) {
    int wi = (blockIdx.x * blockDim.x + threadIdx.x) >> 5;
    int lane = threadIdx.x & 31;
    if (wi >= cnt) return;
    int w = r0 + wi;

    int s = g_start[w];
    int e = g_start[w + 1];

    float ax = 0.f, ay = 0.f, az = 0.f, aw = 0.f;
    #pragma unroll 2
    for (int j = s; j < e; j++) {
        unsigned p = __ldg(&g_pairp[j]);
        float wt = __half2float(__ushort_as_half((unsigned short)(p & 0xffffu)));
        int col = (int)(p >> 16);
        uint2 u = g_S1h[(size_t)col * 32 + lane];
        float2 f0 = __half22float2(*(const __half2*)&u.x);
        float2 f1 = __half22float2(*(const __half2*)&u.y);
        ax += wt * f0.x;
        ay += wt * f0.y;
        az += wt * f1.x;
        aw += wt * f1.y;
    }
    float4 b = __ldg(&b1[lane]);
    __half2 h0 = __floats2half2_rn(fmaxf(ax + b.x, 0.f), fmaxf(ay + b.y, 0.f));
    __half2 h1 = __floats2half2_rn(fmaxf(az + b.z, 0.f), fmaxf(aw + b.w, 0.f));
    uint2 u;
    u.x = *(const unsigned*)&h0;
    u.y = *(const unsigned*)&h1;
    g_hh[(size_t)w * 32 + lane] = u;
}

// ---------------------------------------------------------------------------
// GEMM2 chunk [r0, r0+cnt): g_S2h = fp16(h @ W2), h read as fp16.
// ---------------------------------------------------------------------------
__global__ void __launch_bounds__(320) gemm2_kernel(const float* __restrict__ W2,
                                                    int r0, int cnt) {
    __shared__ float hs[32][129];
    __shared__ float w2s[128 * 40];
    int t = threadIdx.x;

    for (int i = t; i < 128 * 40; i += 320) w2s[i] = W2[i];

    int row0 = r0 + blockIdx.x * 32;
    int hi = r0 + cnt;
    for (int i = t; i < 32 * 32; i += 320) {
        int r = i >> 5, c4 = i & 31;
        int gr = row0 + r;
        uint2 u = (gr < hi) ? g_hh[(size_t)gr * 32 + c4] : make_uint2(0u, 0u);
        float2 f0 = __half22float2(*(const __half2*)&u.x);
        float2 f1 = __half22float2(*(const __half2*)&u.y);
        hs[r][c4 * 4 + 0] = f0.x;
        hs[r][c4 * 4 + 1] = f0.y;
        hs[r][c4 * 4 + 2] = f1.x;
        hs[r][c4 * 4 + 3] = f1.y;
    }
    __syncthreads();

    int col = t % 40;
    int rg  = t / 40;
    float acc[4] = {0.f, 0.f, 0.f, 0.f};
    #pragma unroll 4
    for (int k = 0; k < 128; k++) {
        float wv = w2s[k * 40 + col];
        #pragma unroll
        for (int i = 0; i < 4; i++) acc[i] += hs[rg * 4 + i][k] * wv;
    }
    #pragma unroll
    for (int i = 0; i < 4; i++) {
        int gr = row0 + rg * 4 + i;
        if (gr < hi) g_S2h[(size_t)gr * 40 + col] = __float2half_rn(acc[i]);
    }
}

// ---------------------------------------------------------------------------
// SpMM2: CSR gather + bias + log_softmax. One warp per row.
// ---------------------------------------------------------------------------
__global__ void __launch_bounds__(256) spmm2_csr_kernel(const float* __restrict__ b2,
                                                        float* __restrict__ out,
                                                        int n) {
    int w = (blockIdx.x * blockDim.x + threadIdx.x) >> 5;
    int lane = threadIdx.x & 31;
    if (w >= n) return;

    int s = g_start[w];
    int e = g_start[w + 1];
    bool act = (lane < 20);

    float a0 = 0.f, a1 = 0.f;
    #pragma unroll 2
    for (int j = s; j < e; j++) {
        unsigned p = __ldg(&g_pairp[j]);
        float wt = __half2float(__ushort_as_half((unsigned short)(p & 0xffffu)));
        int col = (int)(p >> 16);
        if (act) {
            __half2 hv = ((const __half2*)(g_S2h + (size_t)col * 40))[lane];
            float2 f = __half22float2(hv);
            a0 += wt * f.x;
            a1 += wt * f.y;
        }
    }

    float v0 = act ? (a0 + __ldg(&b2[2 * lane]))     : -3.0e38f;
    float v1 = act ? (a1 + __ldg(&b2[2 * lane + 1])) : -3.0e38f;

    float m = fmaxf(v0, v1);
    #pragma unroll
    for (int off = 16; off; off >>= 1)
        m = fmaxf(m, __shfl_xor_sync(0xffffffffu, m, off));
    float ssum = act ? (expf(v0 - m) + expf(v1 - m)) : 0.f;
    #pragma unroll
    for (int off = 16; off; off >>= 1)
        ssum += __shfl_xor_sync(0xffffffffu, ssum, off);
    float ls = logf(ssum);

    if (act)
        ((float2*)out)[(size_t)w * 20 + lane] =
            make_float2(v0 - m - ls, v1 - m - ls);
}

// ---------------------------------------------------------------------------
// Launch: fork gemm1 vs CSR build; pipeline spmm1/gemm2 in 2 chunks.
// ---------------------------------------------------------------------------
extern "C" void kernel_launch(void* const* d_in, const int* in_sizes, int n_in,
                              void* d_out, int out_size) {
    const float* x  = (const float*)d_in[0];
    const void*  ei = (const void*) d_in[1];
    const float* ew = (const float*)d_in[2];
    const float* W1 = (const float*)d_in[3];
    const float* b1 = (const float*)d_in[4];
    const float* W2 = (const float*)d_in[5];
    const float* b2 = (const float*)d_in[6];
    float* out = (float*)d_out;

    int n     = in_sizes[0] / 128;   // 50000
    int nedge = in_sizes[2];         // 1600000
    int n2    = n / 2;

    const int GEMM1_SMEM = 2 * 128 * 132 * sizeof(float);   // 135168

    static cudaStream_t s_aux = nullptr;
    static cudaEvent_t ev_fork = nullptr, ev_join = nullptr;
    static cudaEvent_t ev_s1a = nullptr, ev_g2a = nullptr;
    static void* p_cnt = nullptr;
    if (s_aux == nullptr) {
        cudaStreamCreateWithFlags(&s_aux, cudaStreamNonBlocking);
        cudaEventCreateWithFlags(&ev_fork, cudaEventDisableTiming);
        cudaEventCreateWithFlags(&ev_join, cudaEventDisableTiming);
        cudaEventCreateWithFlags(&ev_s1a, cudaEventDisableTiming);
        cudaEventCreateWithFlags(&ev_g2a, cudaEventDisableTiming);
        cudaFuncSetAttribute(gemm1_tc_kernel,
                             cudaFuncAttributeMaxDynamicSharedMemorySize,
                             GEMM1_SMEM);
        cudaGetSymbolAddress(&p_cnt, g_cnt);
    }

    // Fork: gemm1 runs concurrently with CSR build.
    cudaEventRecord(ev_fork, 0);
    cudaStreamWaitEvent(s_aux, ev_fork, 0);
    gemm1_tc_kernel<<<(n + 127) / 128, 256, GEMM1_SMEM, s_aux>>>(x, W1, n);
    cudaEventRecord(ev_join, s_aux);

    // CSR build on stream 0
    detect_kernel<<<1, 32>>>((const int*)ei);
    cudaMemsetAsync(p_cnt, 0, NN * sizeof(int), 0);
    hist_kernel<<<(nedge / 8 + 255) / 256, 256>>>(ei, nedge);
    blocksum_kernel<<<SCAN_G, SCAN_T>>>();
    bscan_kernel<<<1, 64>>>();
    cscan_kernel<<<SCAN_G, SCAN_T>>>();
    scatter_kernel<<<(nedge / 4 + 255) / 256, 256>>>(ei, ew, nedge);

    // Join with gemm1, then pipelined spmm1/gemm2
    cudaStreamWaitEvent(0, ev_join, 0);
    spmm1_csr_kernel<<<(n2 * 32 + 255) / 256, 256>>>((const float4*)b1, 0, n2);
    cudaEventRecord(ev_s1a, 0);
    cudaStreamWaitEvent(s_aux, ev_s1a, 0);
    gemm2_kernel<<<(n2 + 31) / 32, 320, 0, s_aux>>>(W2, 0, n2);
    cudaEventRecord(ev_g2a, s_aux);

    spmm1_csr_kernel<<<((n - n2) * 32 + 255) / 256, 256>>>((const float4*)b1, n2, n - n2);
    gemm2_kernel<<<((n - n2) + 31) / 32, 320>>>(W2, n2, n - n2);

    cudaStreamWaitEvent(0, ev_g2a, 0);
    spmm2_csr_kernel<<<(n * 32 + 255) / 256, 256>>>(b2, out, n);
}

// round 7
// speedup vs baseline: 1.8462x; 1.0019x over previous
#include <cuda_runtime.h>
#include <cuda_fp16.h>

#define NN 50000
#define EE 1600000

#define SCAN_T 256
#define SCAN_PER 4
#define SCAN_CHUNK (SCAN_T * SCAN_PER)                 // 1024
#define SCAN_G ((NN + SCAN_CHUNK - 1) / SCAN_CHUNK)    // 49

// ---------------- scratch ----------------
__device__ uint2          g_S1h[NN * 32];   // x @ W1 as fp16      [N,128]
__device__ uint2          g_hh [NN * 32];   // relu(spmm1+b1) fp16 [N,128]
__device__ __half         g_S2h[NN * 40];   // h @ W2 as fp16      [N,40]
__device__ __align__(16) int g_cnt[NN];
__device__ __align__(16) int g_start[NN + 4];
__device__ unsigned short g_rank[EE];       // rank of edge within its row
__device__ unsigned       g_pairp[EE];      // (col<<16) | fp16(weight), by row
__device__ int            g_bsum[SCAN_G];
__device__ int            g_idx64;

// ---------------------------------------------------------------------------
// init: zero g_cnt (whole grid) + int64/int32 detect (block 0, warp 0)
// ---------------------------------------------------------------------------
__global__ void init_kernel(const int* __restrict__ ei) {
    int i = blockIdx.x * blockDim.x + threadIdx.x;
    if (i < NN) g_cnt[i] = 0;
    if (blockIdx.x == 0 && threadIdx.x < 32) {
        int lane = threadIdx.x;
        int nz0 = (ei[2 * lane + 1] != 0) ? 1 : 0;
        int nz1 = (ei[2 * (lane + 32) + 1] != 0) ? 1 : 0;
        unsigned b = __ballot_sync(0xffffffffu, nz0 | nz1);
        if (lane == 0) g_idx64 = (b == 0u) ? 1 : 0;
    }
}

// ---------------------------------------------------------------------------
// hist: 8 edges/thread; atomicAdd return value IS the edge's rank in its row.
// ---------------------------------------------------------------------------
__global__ void hist_kernel(const void* __restrict__ ei, int nedge) {
    int t = blockIdx.x * blockDim.x + threadIdx.x;
    int e0 = t * 8;
    if (e0 >= nedge) return;
    int r[8];
    if (e0 + 8 <= nedge) {
        if (g_idx64) {
            const int4* p = (const int4*)ei;
            #pragma unroll
            for (int i = 0; i < 4; i++) {
                int4 v = p[t * 4 + i];
                r[2 * i] = v.x; r[2 * i + 1] = v.z;
            }
        } else {
            const int4* p = (const int4*)ei;
            int4 a = p[t * 2], b = p[t * 2 + 1];
            r[0] = a.x; r[1] = a.y; r[2] = a.z; r[3] = a.w;
            r[4] = b.x; r[5] = b.y; r[6] = b.z; r[7] = b.w;
        }
        unsigned rk[8];
        #pragma unroll
        for (int i = 0; i < 8; i++)
            rk[i] = (unsigned)atomicAdd(&g_cnt[r[i]], 1);
        uint4 pk;
        pk.x = rk[0] | (rk[1] << 16);
        pk.y = rk[2] | (rk[3] << 16);
        pk.z = rk[4] | (rk[5] << 16);
        pk.w = rk[6] | (rk[7] << 16);
        *(uint4*)(g_rank + e0) = pk;
    } else {
        for (int i = 0; i < 8 && e0 + i < nedge; i++) {
            int row = g_idx64 ? (int)((const long long*)ei)[e0 + i]
                              : ((const int*)ei)[e0 + i];
            g_rank[e0 + i] = (unsigned short)atomicAdd(&g_cnt[row], 1);
        }
    }
}

// ---------------------------------------------------------------------------
// scan phase 1: per-block sums (49 blocks x 256 threads x 4)
// ---------------------------------------------------------------------------
__global__ void __launch_bounds__(SCAN_T) blocksum_kernel() {
    __shared__ int ws[SCAN_T / 32];
    int t = threadIdx.x;
    int base = blockIdx.x * SCAN_CHUNK + t * SCAN_PER;
    int s = 0;
    #pragma unroll
    for (int i = 0; i < SCAN_PER; i++) {
        int idx = base + i;
        if (idx < NN) s += g_cnt[idx];
    }
    #pragma unroll
    for (int off = 16; off; off >>= 1)
        s += __shfl_xor_sync(0xffffffffu, s, off);
    if ((t & 31) == 0) ws[t >> 5] = s;
    __syncthreads();
    if (t < 32) {
        int v = (t < SCAN_T / 32) ? ws[t] : 0;
        #pragma unroll
        for (int off = 16; off; off >>= 1)
            v += __shfl_xor_sync(0xffffffffu, v, off);
        if (t == 0) g_bsum[blockIdx.x] = v;
    }
}

// ---------------------------------------------------------------------------
// scan phase 2 (merged): each block reduces bsum[0..bid) itself, then local
// exclusive scan + writeback of g_start. Last block writes g_start[NN].
// ---------------------------------------------------------------------------
__global__ void __launch_bounds__(SCAN_T) cscan_kernel() {
    __shared__ int tsum[SCAN_T];
    __shared__ int boff_sh;
    int t = threadIdx.x;
    int bid = blockIdx.x;

    if (t < 32) {
        int v = 0;
        if (t < bid) v += g_bsum[t];
        if (t + 32 < bid) v += g_bsum[t + 32];
        #pragma unroll
        for (int off = 16; off; off >>= 1)
            v += __shfl_xor_sync(0xffffffffu, v, off);
        if (t == 0) boff_sh = v;
    }

    int base = bid * SCAN_CHUNK + t * SCAN_PER;
    int c[SCAN_PER];
    int s = 0;
    #pragma unroll
    for (int i = 0; i < SCAN_PER; i++) {
        int idx = base + i;
        c[i] = (idx < NN) ? g_cnt[idx] : 0;
        s += c[i];
    }
    tsum[t] = s;
    __syncthreads();
    for (int off = 1; off < SCAN_T; off <<= 1) {
        int u = (t >= off) ? tsum[t - off] : 0;
        __syncthreads();
        tsum[t] += u;
        __syncthreads();
    }
    int run = boff_sh + tsum[t] - s;
    #pragma unroll
    for (int i = 0; i < SCAN_PER; i++) {
        int idx = base + i;
        if (idx < NN) {
            g_start[idx] = run;
            run += c[i];
        }
    }
    if (bid == SCAN_G - 1 && t == SCAN_T - 1)
        g_start[NN] = boff_sh + tsum[SCAN_T - 1];
}

// ---------------------------------------------------------------------------
// scatter: atomic-free, 4 edges/thread. pos = start[row] + rank[e].
// ---------------------------------------------------------------------------
__global__ void scatter_kernel(const void* __restrict__ ei,
                               const float* __restrict__ ew, int nedge) {
    int t = blockIdx.x * blockDim.x + threadIdx.x;
    int e0 = t * 4;
    if (e0 >= nedge) return;
    if (e0 + 4 <= nedge) {
        int r[4], c[4];
        if (g_idx64) {
            const int4* p = (const int4*)ei;
            int4 a = p[t * 2], b = p[t * 2 + 1];
            r[0] = a.x; r[1] = a.z; r[2] = b.x; r[3] = b.z;
            const int4* q = p + (size_t)nedge / 2;
            int4 ca = q[t * 2], cb = q[t * 2 + 1];
            c[0] = ca.x; c[1] = ca.z; c[2] = cb.x; c[3] = cb.z;
        } else {
            const int4* p = (const int4*)ei;
            int4 a = p[t];
            r[0] = a.x; r[1] = a.y; r[2] = a.z; r[3] = a.w;
            int4 ca = p[nedge / 4 + t];
            c[0] = ca.x; c[1] = ca.y; c[2] = ca.z; c[3] = ca.w;
        }
        float4 w = ((const float4*)ew)[t];
        float wv[4] = {w.x, w.y, w.z, w.w};
        ushort4 rk = *(const ushort4*)(g_rank + e0);
        unsigned short rka[4] = {rk.x, rk.y, rk.z, rk.w};
        #pragma unroll
        for (int i = 0; i < 4; i++) {
            int pos = g_start[r[i]] + (int)rka[i];
            g_pairp[pos] = ((unsigned)c[i] << 16) |
                           (unsigned)__half_as_ushort(__float2half_rn(wv[i]));
        }
    } else {
        for (int i = 0; i < 4 && e0 + i < nedge; i++) {
            int row, col;
            if (g_idx64) {
                row = (int)((const long long*)ei)[e0 + i];
                col = (int)((const long long*)ei)[nedge + e0 + i];
            } else {
                row = ((const int*)ei)[e0 + i];
                col = ((const int*)ei)[nedge + e0 + i];
            }
            int pos = g_start[row] + (int)g_rank[e0 + i];
            g_pairp[pos] = ((unsigned)col << 16) |
                           (unsigned)__half_as_ushort(__float2half_rn(ew[e0 + i]));
        }
    }
}

// ---------------------------------------------------------------------------
// GEMM1 (tf32 tensor cores): g_S1h = fp16(x @ W1), tile 128x128, K=128
// ---------------------------------------------------------------------------
__device__ __forceinline__ unsigned f2tf32(float f) {
    unsigned u;
    asm("cvt.rna.tf32.f32 %0, %1;" : "=r"(u) : "f"(f));
    return u;
}

__global__ void __launch_bounds__(256) gemm1_tc_kernel(const float* __restrict__ x,
                                                       const float* __restrict__ W1,
                                                       int n) {
    extern __shared__ float smem[];
    float (*xs)[132] = (float(*)[132])smem;
    float (*ws)[132] = (float(*)[132])(smem + 128 * 132);

    int t = threadIdx.x;
    int row0 = blockIdx.x * 128;

    const float4* X4 = (const float4*)x;
    const float4* W4 = (const float4*)W1;
    for (int i = t; i < 128 * 32; i += 256) {
        int r = i >> 5, c4 = i & 31;
        int gr = row0 + r;
        float4 v = (gr < n) ? X4[(size_t)gr * 32 + c4]
                            : make_float4(0.f, 0.f, 0.f, 0.f);
        *(float4*)&xs[r][c4 * 4] = v;
    }
    for (int i = t; i < 128 * 32; i += 256) {
        int r = i >> 5, c4 = i & 31;
        *(float4*)&ws[r][c4 * 4] = W4[r * 32 + c4];
    }
    __syncthreads();

    int lane = t & 31;
    int wid  = t >> 5;
    int mw = wid >> 1;
    int nw = wid & 1;

    float acc[2][8][4];
    #pragma unroll
    for (int a = 0; a < 2; a++)
        #pragma unroll
        for (int b = 0; b < 8; b++)
            #pragma unroll
            for (int c = 0; c < 4; c++) acc[a][b][c] = 0.f;

    int lr = lane >> 2;
    int lc = lane & 3;

    #pragma unroll 1
    for (int kt = 0; kt < 16; kt++) {
        int k = kt * 8;
        unsigned A[2][4];
        #pragma unroll
        for (int mt = 0; mt < 2; mt++) {
            int r = mw * 32 + mt * 16 + lr;
            A[mt][0] = f2tf32(xs[r    ][k + lc]);
            A[mt][1] = f2tf32(xs[r + 8][k + lc]);
            A[mt][2] = f2tf32(xs[r    ][k + lc + 4]);
            A[mt][3] = f2tf32(xs[r + 8][k + lc + 4]);
        }
        #pragma unroll
        for (int nt = 0; nt < 8; nt++) {
            int cn = nw * 64 + nt * 8 + lr;
            unsigned b0 = f2tf32(ws[k + lc    ][cn]);
            unsigned b1 = f2tf32(ws[k + lc + 4][cn]);
            #pragma unroll
            for (int mt = 0; mt < 2; mt++) {
                asm volatile(
                    "mma.sync.aligned.m16n8k8.row.col.f32.tf32.tf32.f32 "
                    "{%0,%1,%2,%3}, {%4,%5,%6,%7}, {%8,%9}, {%0,%1,%2,%3};"
                    : "+f"(acc[mt][nt][0]), "+f"(acc[mt][nt][1]),
                      "+f"(acc[mt][nt][2]), "+f"(acc[mt][nt][3])
                    : "r"(A[mt][0]), "r"(A[mt][1]), "r"(A[mt][2]), "r"(A[mt][3]),
                      "r"(b0), "r"(b1));
            }
        }
    }

    __half2* dst = (__half2*)g_S1h;
    #pragma unroll
    for (int mt = 0; mt < 2; mt++) {
        #pragma unroll
        for (int nt = 0; nt < 8; nt++) {
            int row = row0 + mw * 32 + mt * 16 + lr;
            int col = nw * 64 + nt * 8 + lc * 2;
            if (row < n)
                dst[(size_t)row * 64 + (col >> 1)] =
                    __floats2half2_rn(acc[mt][nt][0], acc[mt][nt][1]);
            if (row + 8 < n)
                dst[(size_t)(row + 8) * 64 + (col >> 1)] =
                    __floats2half2_rn(acc[mt][nt][2], acc[mt][nt][3]);
        }
    }
}

// ---------------------------------------------------------------------------
// SpMM1 chunk [r0, r0+cnt): CSR gather + bias + ReLU, fp16 in/out.
// Two independent accumulator banks (even/odd edge) for ILP.
// ---------------------------------------------------------------------------
__global__ void __launch_bounds__(256) spmm1_csr_kernel(const float4* __restrict__ b1,
                                                        int r0, int cnt) {
    int wi = (blockIdx.x * blockDim.x + threadIdx.x) >> 5;
    int lane = threadIdx.x & 31;
    if (wi >= cnt) return;
    int w = r0 + wi;

    const unsigned* __restrict__ pp = g_pairp;
    const uint2*    __restrict__ S  = g_S1h;

    int s = g_start[w];
    int e = g_start[w + 1];

    float ax0 = 0.f, ay0 = 0.f, az0 = 0.f, aw0 = 0.f;
    float ax1 = 0.f, ay1 = 0.f, az1 = 0.f, aw1 = 0.f;
    int j = s;
    for (; j + 2 <= e; j += 2) {
        unsigned p0 = __ldg(&pp[j]);
        unsigned p1 = __ldg(&pp[j + 1]);
        uint2 u0 = __ldg(&S[(size_t)(p0 >> 16) * 32 + lane]);
        uint2 u1 = __ldg(&S[(size_t)(p1 >> 16) * 32 + lane]);
        float wt0 = __half2float(__ushort_as_half((unsigned short)(p0 & 0xffffu)));
        float wt1 = __half2float(__ushort_as_half((unsigned short)(p1 & 0xffffu)));
        float2 f00 = __half22float2(*(const __half2*)&u0.x);
        float2 f01 = __half22float2(*(const __half2*)&u0.y);
        float2 f10 = __half22float2(*(const __half2*)&u1.x);
        float2 f11 = __half22float2(*(const __half2*)&u1.y);
        ax0 += wt0 * f00.x;  ay0 += wt0 * f00.y;
        az0 += wt0 * f01.x;  aw0 += wt0 * f01.y;
        ax1 += wt1 * f10.x;  ay1 += wt1 * f10.y;
        az1 += wt1 * f11.x;  aw1 += wt1 * f11.y;
    }
    if (j < e) {
        unsigned p = __ldg(&pp[j]);
        float wt = __half2float(__ushort_as_half((unsigned short)(p & 0xffffu)));
        uint2 u = __ldg(&S[(size_t)(p >> 16) * 32 + lane]);
        float2 f0 = __half22float2(*(const __half2*)&u.x);
        float2 f1 = __half22float2(*(const __half2*)&u.y);
        ax0 += wt * f0.x;  ay0 += wt * f0.y;
        az0 += wt * f1.x;  aw0 += wt * f1.y;
    }
    float ax = ax0 + ax1, ay = ay0 + ay1, az = az0 + az1, aw = aw0 + aw1;

    float4 b = __ldg(&b1[lane]);
    __half2 h0 = __floats2half2_rn(fmaxf(ax + b.x, 0.f), fmaxf(ay + b.y, 0.f));
    __half2 h1 = __floats2half2_rn(fmaxf(az + b.z, 0.f), fmaxf(aw + b.w, 0.f));
    uint2 u;
    u.x = *(const unsigned*)&h0;
    u.y = *(const unsigned*)&h1;
    g_hh[(size_t)w * 32 + lane] = u;
}

// ---------------------------------------------------------------------------
// GEMM2 chunk [r0, r0+cnt): g_S2h = fp16(h @ W2), h read as fp16.
// ---------------------------------------------------------------------------
__global__ void __launch_bounds__(320) gemm2_kernel(const float* __restrict__ W2,
                                                    int r0, int cnt) {
    __shared__ float hs[32][129];
    __shared__ float w2s[128 * 40];
    int t = threadIdx.x;

    for (int i = t; i < 128 * 40; i += 320) w2s[i] = W2[i];

    int row0 = r0 + blockIdx.x * 32;
    int hi = r0 + cnt;
    for (int i = t; i < 32 * 32; i += 320) {
        int r = i >> 5, c4 = i & 31;
        int gr = row0 + r;
        uint2 u = (gr < hi) ? g_hh[(size_t)gr * 32 + c4] : make_uint2(0u, 0u);
        float2 f0 = __half22float2(*(const __half2*)&u.x);
        float2 f1 = __half22float2(*(const __half2*)&u.y);
        hs[r][c4 * 4 + 0] = f0.x;
        hs[r][c4 * 4 + 1] = f0.y;
        hs[r][c4 * 4 + 2] = f1.x;
        hs[r][c4 * 4 + 3] = f1.y;
    }
    __syncthreads();

    int col = t % 40;
    int rg  = t / 40;
    float acc[4] = {0.f, 0.f, 0.f, 0.f};
    #pragma unroll 4
    for (int k = 0; k < 128; k++) {
        float wv = w2s[k * 40 + col];
        #pragma unroll
        for (int i = 0; i < 4; i++) acc[i] += hs[rg * 4 + i][k] * wv;
    }
    #pragma unroll
    for (int i = 0; i < 4; i++) {
        int gr = row0 + rg * 4 + i;
        if (gr < hi) g_S2h[(size_t)gr * 40 + col] = __float2half_rn(acc[i]);
    }
}

// ---------------------------------------------------------------------------
// SpMM2: CSR gather + bias + log_softmax. One warp per row.
// ---------------------------------------------------------------------------
__global__ void __launch_bounds__(256) spmm2_csr_kernel(const float* __restrict__ b2,
                                                        float* __restrict__ out,
                                                        int n) {
    int w = (blockIdx.x * blockDim.x + threadIdx.x) >> 5;
    int lane = threadIdx.x & 31;
    if (w >= n) return;

    const unsigned* __restrict__ pp = g_pairp;
    int s = g_start[w];
    int e = g_start[w + 1];
    bool act = (lane < 20);

    float a0 = 0.f, a1 = 0.f;
    #pragma unroll 2
    for (int j = s; j < e; j++) {
        unsigned p = __ldg(&pp[j]);
        float wt = __half2float(__ushort_as_half((unsigned short)(p & 0xffffu)));
        int col = (int)(p >> 16);
        if (act) {
            __half2 hv = ((const __half2*)(g_S2h + (size_t)col * 40))[lane];
            float2 f = __half22float2(hv);
            a0 += wt * f.x;
            a1 += wt * f.y;
        }
    }

    float v0 = act ? (a0 + __ldg(&b2[2 * lane]))     : -3.0e38f;
    float v1 = act ? (a1 + __ldg(&b2[2 * lane + 1])) : -3.0e38f;

    float m = fmaxf(v0, v1);
    #pragma unroll
    for (int off = 16; off; off >>= 1)
        m = fmaxf(m, __shfl_xor_sync(0xffffffffu, m, off));
    float ssum = act ? (expf(v0 - m) + expf(v1 - m)) : 0.f;
    #pragma unroll
    for (int off = 16; off; off >>= 1)
        ssum += __shfl_xor_sync(0xffffffffu, ssum, off);
    float ls = logf(ssum);

    if (act)
        ((float2*)out)[(size_t)w * 20 + lane] =
            make_float2(v0 - m - ls, v1 - m - ls);
}

// ---------------------------------------------------------------------------
// Launch: fork gemm1 vs CSR build; pipeline spmm1/gemm2 in 2 chunks.
// ---------------------------------------------------------------------------
extern "C" void kernel_launch(void* const* d_in, const int* in_sizes, int n_in,
                              void* d_out, int out_size) {
    const float* x  = (const float*)d_in[0];
    const void*  ei = (const void*) d_in[1];
    const float* ew = (const float*)d_in[2];
    const float* W1 = (const float*)d_in[3];
    const float* b1 = (const float*)d_in[4];
    const float* W2 = (const float*)d_in[5];
    const float* b2 = (const float*)d_in[6];
    float* out = (float*)d_out;

    int n     = in_sizes[0] / 128;   // 50000
    int nedge = in_sizes[2];         // 1600000
    int n2    = n / 2;

    const int GEMM1_SMEM = 2 * 128 * 132 * sizeof(float);   // 135168

    static cudaStream_t s_aux = nullptr;
    static cudaEvent_t ev_fork = nullptr, ev_join = nullptr;
    static cudaEvent_t ev_s1a = nullptr, ev_g2a = nullptr;
    if (s_aux == nullptr) {
        cudaStreamCreateWithFlags(&s_aux, cudaStreamNonBlocking);
        cudaEventCreateWithFlags(&ev_fork, cudaEventDisableTiming);
        cudaEventCreateWithFlags(&ev_join, cudaEventDisableTiming);
        cudaEventCreateWithFlags(&ev_s1a, cudaEventDisableTiming);
        cudaEventCreateWithFlags(&ev_g2a, cudaEventDisableTiming);
        cudaFuncSetAttribute(gemm1_tc_kernel,
                             cudaFuncAttributeMaxDynamicSharedMemorySize,
                             GEMM1_SMEM);
    }

    // Fork: gemm1 runs concurrently with CSR build.
    cudaEventRecord(ev_fork, 0);
    cudaStreamWaitEvent(s_aux, ev_fork, 0);
    gemm1_tc_kernel<<<(n + 127) / 128, 256, GEMM1_SMEM, s_aux>>>(x, W1, n);
    cudaEventRecord(ev_join, s_aux);

    // CSR build on stream 0
    init_kernel<<<(NN + 1023) / 1024, 1024>>>((const int*)ei);
    hist_kernel<<<(nedge / 8 + 255) / 256, 256>>>(ei, nedge);
    blocksum_kernel<<<SCAN_G, SCAN_T>>>();
    cscan_kernel<<<SCAN_G, SCAN_T>>>();
    scatter_kernel<<<(nedge / 4 + 255) / 256, 256>>>(ei, ew, nedge);

    // Join with gemm1, then pipelined spmm1/gemm2
    cudaStreamWaitEvent(0, ev_join, 0);
    spmm1_csr_kernel<<<(n2 * 32 + 255) / 256, 256>>>((const float4*)b1, 0, n2);
    cudaEventRecord(ev_s1a, 0);
    cudaStreamWaitEvent(s_aux, ev_s1a, 0);
    gemm2_kernel<<<(n2 + 31) / 32, 320, 0, s_aux>>>(W2, 0, n2);
    cudaEventRecord(ev_g2a, s_aux);

    spmm1_csr_kernel<<<((n - n2) * 32 + 255) / 256, 256>>>((const float4*)b1, n2, n - n2);
    gemm2_kernel<<<((n - n2) + 31) / 32, 320>>>(W2, n2, n - n2);

    cudaStreamWaitEvent(0, ev_g2a, 0);
    spmm2_csr_kernel<<<(n * 32 + 255) / 256, 256>>>(b2, out, n);
}